// round 7
// baseline (speedup 1.0000x reference)
#include <cuda_runtime.h>
#include <cuda_bf16.h>
#include <math.h>
#include <stdint.h>

#define BB   8
#define SS   2048
#define DD   512
#define DKK  64
#define DFFN 2048
#define NREP 6
#define MSROWS (BB*SS)          // 16384
#define NTOT (BB*SS*DD)         // 8388608

typedef __nv_bfloat16 bf16;
typedef signed char s8;

// ---------------------------------------------------------------------------
// Scratch
// ---------------------------------------------------------------------------
__device__ float g_x   [NTOT];
__device__ float g_x1  [NTOT];
__device__ float g_y   [NTOT];
__device__ float g_h   [(long)MSROWS*DFFN];   // fp32 FFN hidden (134MB)

__device__ bf16 g_xh [NTOT];
__device__ bf16 g_xl [NTOT];
__device__ bf16 g_qkvh[MSROWS*192];
__device__ bf16 g_qkvl[MSROWS*192];
__device__ bf16 g_vTh[BB*DKK*SS];
__device__ bf16 g_vTl[BB*DKK*SS];
__device__ bf16 g_headh[MSROWS*DKK];
__device__ bf16 g_headl[MSROWS*DKK];
__device__ bf16 g_probsh[(long)BB*SS*SS];
__device__ bf16 g_probsl[(long)BB*SS*SS];

__device__ bf16 g_wqkvTh[192*DD];
__device__ bf16 g_wqkvTl[192*DD];
__device__ bf16 g_woTh[DD*DKK];
__device__ bf16 g_woTl[DD*DKK];
__device__ float g_bqkv[192];

// int8 2-limb FFN operands
__device__ s8   g_x1q0[MSROWS*DD];
__device__ s8   g_x1q1[MSROWS*DD];
__device__ float g_sx1[MSROWS];
__device__ s8   g_hq0[(long)MSROWS*DFFN];
__device__ s8   g_hq1[(long)MSROWS*DFFN];
__device__ float g_sh[MSROWS];
__device__ s8   g_w1q0[DFFN*DD];
__device__ s8   g_w1q1[DFFN*DD];
__device__ float g_sw1[DFFN];
__device__ s8   g_w2q0[DD*DFFN];
__device__ s8   g_w2q1[DD*DFFN];
__device__ float g_sw2[DD];

__device__ float g_rpart[MSROWS*16];
__device__ float g_rinv [MSROWS];
__device__ float g_psum[1024];
__device__ float g_psq [1024];
__device__ float g_stats[2];

// ---------------------------------------------------------------------------
// Helpers
// ---------------------------------------------------------------------------
__device__ __forceinline__ uint32_t cvta_shared_u32(const void* p) {
    uint32_t a;
    asm("{ .reg .u64 t; cvta.to.shared.u64 t, %1; cvt.u32.u64 %0, t; }" : "=r"(a) : "l"(p));
    return a;
}
__device__ __forceinline__ void cp_async16(uint32_t saddr, const void* gptr) {
    asm volatile("cp.async.cg.shared.global [%0], [%1], 16;" :: "r"(saddr), "l"(gptr));
}
__device__ __forceinline__ void cp_commit() {
    asm volatile("cp.async.commit_group;" ::: "memory");
}
template<int N>
__device__ __forceinline__ void cp_wait() {
    asm volatile("cp.async.wait_group %0;" :: "n"(N) : "memory");
}
__device__ __forceinline__ void ldsm_x4(uint32_t& r0, uint32_t& r1, uint32_t& r2, uint32_t& r3,
                                        uint32_t addr) {
    asm volatile("ldmatrix.sync.aligned.m8n8.x4.shared.b16 {%0,%1,%2,%3}, [%4];"
                 : "=r"(r0), "=r"(r1), "=r"(r2), "=r"(r3) : "r"(addr));
}
__device__ __forceinline__ void split_bf16(float e0, float e1, uint32_t& hi, uint32_t& lo) {
    asm("cvt.rn.bf16x2.f32 %0, %1, %2;" : "=r"(hi) : "f"(e1), "f"(e0));
    float h0 = __uint_as_float(hi << 16);
    float h1 = __uint_as_float(hi & 0xffff0000u);
    float l0 = e0 - h0;
    float l1 = e1 - h1;
    asm("cvt.rn.bf16x2.f32 %0, %1, %2;" : "=r"(lo) : "f"(l1), "f"(l0));
}
__device__ __forceinline__ void split1(float v, bf16& h, bf16& l) {
    h = __float2bfloat16_rn(v);
    l = __float2bfloat16_rn(v - __bfloat162float(h));
}
__device__ __forceinline__ void mma_bf16(float* c, const uint32_t* a, const uint32_t* b) {
    asm volatile(
        "mma.sync.aligned.m16n8k16.row.col.f32.bf16.bf16.f32 "
        "{%0,%1,%2,%3}, {%4,%5,%6,%7}, {%8,%9}, {%0,%1,%2,%3};"
        : "+f"(c[0]), "+f"(c[1]), "+f"(c[2]), "+f"(c[3])
        : "r"(a[0]), "r"(a[1]), "r"(a[2]), "r"(a[3]), "r"(b[0]), "r"(b[1]));
}
__device__ __forceinline__ void mma_s8(int* c, const uint32_t* a, const uint32_t* b) {
    asm volatile(
        "mma.sync.aligned.m16n8k32.row.col.s32.s8.s8.s32 "
        "{%0,%1,%2,%3}, {%4,%5,%6,%7}, {%8,%9}, {%0,%1,%2,%3};"
        : "+r"(c[0]), "+r"(c[1]), "+r"(c[2]), "+r"(c[3])
        : "r"(a[0]), "r"(a[1]), "r"(a[2]), "r"(a[3]), "r"(b[0]), "r"(b[1]));
}

// ---------------------------------------------------------------------------
// bf16 pre-split GEMM (attention path). Modes:
// 0: C fp32 = acc*alpha + bias + src, + LN partials
// 1: Chi/Clo = split(acc*alpha + bias)
// 2: Chi/Clo = split(exp(acc*alpha)), row partial sums -> rpart
// 3: Chi/Clo = split(acc * rinv[row])
// ---------------------------------------------------------------------------
#define SMSB 40

template<int BN, int WM, int WN, int STAGES, int MODE>
__global__ void __launch_bounds__(256, 2)
mma_gemm(const bf16* __restrict__ Ahi, const bf16* __restrict__ Alo, int lda, long strideA,
         const bf16* __restrict__ Bhi, const bf16* __restrict__ Blo, int ldb, long strideB,
         const float* __restrict__ bias, const float* __restrict__ src,
         float* __restrict__ C, bf16* __restrict__ Chi, bf16* __restrict__ Clo,
         int ldc, long strideC, int K, float alpha,
         float* __restrict__ rpart, const float* __restrict__ rinv,
         float* __restrict__ psum, float* __restrict__ psq)
{
    constexpr int MT = WM / 16;
    constexpr int NT = WN / 8;
    constexpr int WARPS_N = BN / WN;
    static_assert((128 / WM) * (BN / WN) == 8, "8 warps");
    static_assert(NT % 2 == 0, "NT even");

    constexpr int OFF_ALO = 128 * SMSB;
    constexpr int OFF_BHI = 256 * SMSB;
    constexpr int OFF_BLO = OFF_BHI + BN * SMSB;
    constexpr int BUFSZ   = OFF_BLO + BN * SMSB;

    extern __shared__ bf16 smem[];
    __shared__ float s_red0[256];
    __shared__ float s_red1[256];
    __shared__ float s_rows[4][128];

    const int tid  = threadIdx.x;
    const int lane = tid & 31;
    const int wid  = tid >> 5;
    const int warp_m = wid / WARPS_N;
    const int warp_n = wid % WARPS_N;
    const int qr = lane >> 2;
    const int qc = lane & 3;

    const long bz = blockIdx.z;
    Ahi += bz * strideA;  Alo += bz * strideA;
    Bhi += bz * strideB;  Blo += bz * strideB;
    if (MODE == 0 && C) C += bz * strideC;
    if (Chi) { Chi += bz * strideC; Clo += bz * strideC; }
    const float* srcp = (MODE == 0 && src) ? src + bz * strideC : (const float*)0;

    const int m0 = blockIdx.y * 128;
    const int n0 = blockIdx.x * BN;

    float acc[MT][NT][4];
#pragma unroll
    for (int i = 0; i < MT; i++)
#pragma unroll
        for (int j = 0; j < NT; j++)
#pragma unroll
            for (int u = 0; u < 4; u++) acc[i][j][u] = 0.f;

    const uint32_t sb = cvta_shared_u32(smem);

    auto load_chunk = [&](int c, int stg) {
        const int k0 = c << 5;
        const uint32_t base = sb + (uint32_t)stg * (BUFSZ * 2);
#pragma unroll
        for (int i = 0; i < 2; i++) {
            int idx = tid + i * 256;
            int row = idx >> 2, c8 = idx & 3;
            long g = (long)(m0 + row) * lda + k0 + c8 * 8;
            uint32_t so = (uint32_t)(row * SMSB + c8 * 8) * 2;
            cp_async16(base + so, Ahi + g);
            cp_async16(base + OFF_ALO * 2 + so, Alo + g);
        }
#pragma unroll
        for (int i = 0; i < BN / 64; i++) {
            int idx = tid + i * 256;
            int row = idx >> 2, c8 = idx & 3;
            long g = (long)(n0 + row) * ldb + k0 + c8 * 8;
            uint32_t so = (uint32_t)(row * SMSB + c8 * 8) * 2;
            cp_async16(base + OFF_BHI * 2 + so, Bhi + g);
            cp_async16(base + OFF_BLO * 2 + so, Blo + g);
        }
    };

    const int nch = K >> 5;
#pragma unroll
    for (int s = 0; s < STAGES - 1; s++) { load_chunk(s, s); cp_commit(); }

    const uint32_t a_off = (uint32_t)(((lane & 15) + warp_m * WM) * SMSB + (lane >> 4) * 8) * 2;
    const uint32_t b_off = (uint32_t)((((lane >> 4) & 1) * 8 + (lane & 7) + warp_n * WN) * SMSB
                                      + ((lane >> 3) & 1) * 8) * 2;

    for (int c = 0; c < nch; c++) {
        const int stg = c % STAGES;
        if (c + STAGES - 1 < nch) {
            load_chunk(c + STAGES - 1, (c + STAGES - 1) % STAGES);
            cp_commit();
            cp_wait<STAGES - 1>();
        } else {
            cp_wait<0>();
        }
        __syncthreads();

        const uint32_t stA  = sb + (uint32_t)stg * (BUFSZ * 2);
        const uint32_t stAl = stA + OFF_ALO * 2;
        const uint32_t stBh = stA + OFF_BHI * 2;
        const uint32_t stBl = stA + OFF_BLO * 2;

#pragma unroll
        for (int ks = 0; ks < 2; ks++) {
            const uint32_t kk2 = (uint32_t)ks * 32;
            uint32_t bh[NT][2], bl[NT][2];
#pragma unroll
            for (int in2 = 0; in2 < NT / 2; in2++) {
                uint32_t off = b_off + (uint32_t)in2 * (16 * SMSB * 2) + kk2;
                ldsm_x4(bh[2*in2][0], bh[2*in2][1], bh[2*in2+1][0], bh[2*in2+1][1], stBh + off);
                ldsm_x4(bl[2*in2][0], bl[2*in2][1], bl[2*in2+1][0], bl[2*in2+1][1], stBl + off);
            }
#pragma unroll
            for (int im = 0; im < MT; im++) {
                uint32_t off = a_off + (uint32_t)im * (16 * SMSB * 2) + kk2;
                uint32_t ah[4], al[4];
                ldsm_x4(ah[0], ah[1], ah[2], ah[3], stA + off);
                ldsm_x4(al[0], al[1], al[2], al[3], stAl + off);
#pragma unroll
                for (int in_ = 0; in_ < NT; in_++) {
                    mma_bf16(acc[im][in_], ah, bh[in_]);
                    mma_bf16(acc[im][in_], al, bh[in_]);
                    mma_bf16(acc[im][in_], ah, bl[in_]);
                }
            }
        }
        __syncthreads();
    }

    float lsum = 0.f, lsq = 0.f;
    const float* rinvp = (MODE == 3) ? rinv + bz * SS : (const float*)0;

#pragma unroll
    for (int im = 0; im < MT; im++) {
#pragma unroll
        for (int h2 = 0; h2 < 2; h2++) {
            const int rloc = warp_m * WM + im * 16 + qr + h2 * 8;
            const int row  = m0 + rloc;
            float rs = 0.f;
            float rv = 0.f;
            if (MODE == 3) rv = rinvp[row];
#pragma unroll
            for (int in_ = 0; in_ < NT; in_++) {
                const int col = n0 + warp_n * WN + in_ * 8 + qc * 2;
                float v0 = acc[im][in_][h2 * 2 + 0] * alpha;
                float v1 = acc[im][in_][h2 * 2 + 1] * alpha;
                if (MODE == 0 || MODE == 1) {
                    if (bias) { v0 += bias[col]; v1 += bias[col + 1]; }
                }
                if (MODE == 0) {
                    if (srcp) {
                        float2 s2 = *reinterpret_cast<const float2*>(&srcp[(long)row * ldc + col]);
                        v0 += s2.x; v1 += s2.y;
                    }
                    float2 o; o.x = v0; o.y = v1;
                    *reinterpret_cast<float2*>(&C[(long)row * ldc + col]) = o;
                    lsum += v0 + v1;
                    lsq  += v0 * v0 + v1 * v1;
                } else {
                    if (MODE == 2) { v0 = __expf(v0); v1 = __expf(v1); rs += v0 + v1; }
                    if (MODE == 3) { v0 *= rv; v1 *= rv; }
                    uint32_t hp, lp;
                    split_bf16(v0, v1, hp, lp);
                    *reinterpret_cast<uint32_t*>(&Chi[(long)row * ldc + col]) = hp;
                    *reinterpret_cast<uint32_t*>(&Clo[(long)row * ldc + col]) = lp;
                }
            }
            if (MODE == 2) {
                rs += __shfl_xor_sync(0xffffffffu, rs, 1);
                rs += __shfl_xor_sync(0xffffffffu, rs, 2);
                if ((lane & 3) == 0) s_rows[warp_n][rloc] = rs;
            }
        }
    }

    if (MODE == 2) {
        __syncthreads();
        if (tid < 128) {
            float s = 0.f;
#pragma unroll
            for (int wn = 0; wn < WARPS_N; wn++) s += s_rows[wn][tid];
            long rg = bz * SS + m0 + tid;
            rpart[rg * 16 + blockIdx.x] = s;
        }
    }
    if (MODE == 0) {
        s_red0[tid] = lsum; s_red1[tid] = lsq;
        __syncthreads();
        for (int s = 128; s > 0; s >>= 1) {
            if (tid < s) { s_red0[tid] += s_red0[tid + s]; s_red1[tid] += s_red1[tid + s]; }
            __syncthreads();
        }
        if (tid == 0) {
            int cta = blockIdx.y * gridDim.x + blockIdx.x;
            psum[cta] = s_red0[0];
            psq [cta] = s_red1[0];
        }
    }
}

// ---------------------------------------------------------------------------
// int8 2-limb IMMA GEMM (FFN path): C = sA[m]·sB[n]·(P + Q/256) + bias (+src, LN) | ReLU
//   A limbs [M,K], B limbs [N,K], K mult of 64. BM=128, BN=64, 8 warps (4x2).
//   Smem rows: 64 bytes used, stride 80 (conflict-free ldmatrix).
// ---------------------------------------------------------------------------
#define SMSQ 80

template<bool RELU, bool LN>
__global__ void __launch_bounds__(256, 2)
imma_gemm(const s8* __restrict__ A0, const s8* __restrict__ A1,
          const float* __restrict__ sA, int lda,
          const s8* __restrict__ B0, const s8* __restrict__ B1,
          const float* __restrict__ sB, int ldb,
          const float* __restrict__ bias, const float* __restrict__ src,
          float* __restrict__ C, int ldc, int K,
          float* __restrict__ psum, float* __restrict__ psq)
{
    constexpr int BN = 64, WM = 32, WN = 32;
    constexpr int MT = 2, NT = 4;
    constexpr int STAGES = 3;
    constexpr int OFF_A1 = 128 * SMSQ;          // bytes
    constexpr int OFF_B0 = 256 * SMSQ;
    constexpr int OFF_B1 = OFF_B0 + BN * SMSQ;
    constexpr int BUFSZ  = OFF_B1 + BN * SMSQ;  // bytes per stage

    extern __shared__ char smq[];
    __shared__ float s_red0[256];
    __shared__ float s_red1[256];

    const int tid  = threadIdx.x;
    const int lane = tid & 31;
    const int wid  = tid >> 5;
    const int warp_m = wid >> 1;       // 0..3
    const int warp_n = wid & 1;        // 0..1
    const int qr = lane >> 2;
    const int qc = lane & 3;

    const int m0 = blockIdx.y * 128;
    const int n0 = blockIdx.x * BN;

    int accP[MT][NT][4], accQ[MT][NT][4];
#pragma unroll
    for (int i = 0; i < MT; i++)
#pragma unroll
        for (int j = 0; j < NT; j++)
#pragma unroll
            for (int u = 0; u < 4; u++) { accP[i][j][u] = 0; accQ[i][j][u] = 0; }

    const uint32_t sb = cvta_shared_u32(smq);

    auto load_chunk = [&](int c, int stg) {
        const int k0 = c << 6;                       // 64 bytes per chunk
        const uint32_t base = sb + (uint32_t)stg * BUFSZ;
#pragma unroll
        for (int i = 0; i < 2; i++) {                // A: 128 rows x 4 segs
            int idx = tid + i * 256;
            int row = idx >> 2, sg = idx & 3;
            long g = (long)(m0 + row) * lda + k0 + sg * 16;
            uint32_t so = (uint32_t)(row * SMSQ + sg * 16);
            cp_async16(base + so, A0 + g);
            cp_async16(base + OFF_A1 + so, A1 + g);
        }
        {                                            // B: 64 rows x 4 segs
            int row = tid >> 2, sg = tid & 3;
            long g = (long)(n0 + row) * ldb + k0 + sg * 16;
            uint32_t so = (uint32_t)(row * SMSQ + sg * 16);
            cp_async16(base + OFF_B0 + so, B0 + g);
            cp_async16(base + OFF_B1 + so, B1 + g);
        }
    };

    const int nch = K >> 6;
#pragma unroll
    for (int s = 0; s < STAGES - 1; s++) { load_chunk(s, s); cp_commit(); }

    const uint32_t a_off = (uint32_t)(((lane & 15) + warp_m * WM) * SMSQ + (lane >> 4) * 16);
    const uint32_t b_off = (uint32_t)((((lane >> 4) & 1) * 8 + (lane & 7) + warp_n * WN) * SMSQ
                                      + ((lane >> 3) & 1) * 16);

    for (int c = 0; c < nch; c++) {
        const int stg = c % STAGES;
        if (c + STAGES - 1 < nch) {
            load_chunk(c + STAGES - 1, (c + STAGES - 1) % STAGES);
            cp_commit();
            cp_wait<STAGES - 1>();
        } else {
            cp_wait<0>();
        }
        __syncthreads();

        const uint32_t stA0 = sb + (uint32_t)stg * BUFSZ;
        const uint32_t stA1 = stA0 + OFF_A1;
        const uint32_t stB0 = stA0 + OFF_B0;
        const uint32_t stB1 = stA0 + OFF_B1;

#pragma unroll
        for (int ks = 0; ks < 2; ks++) {             // 2 x k32 per 64B chunk
            const uint32_t kk = (uint32_t)ks * 32;
            uint32_t b0[NT][2], b1[NT][2];
#pragma unroll
            for (int in2 = 0; in2 < NT / 2; in2++) {
                uint32_t off = b_off + (uint32_t)in2 * (16 * SMSQ) + kk;
                ldsm_x4(b0[2*in2][0], b0[2*in2][1], b0[2*in2+1][0], b0[2*in2+1][1], stB0 + off);
                ldsm_x4(b1[2*in2][0], b1[2*in2][1], b1[2*in2+1][0], b1[2*in2+1][1], stB1 + off);
            }
#pragma unroll
            for (int im = 0; im < MT; im++) {
                uint32_t off = a_off + (uint32_t)im * (16 * SMSQ) + kk;
                uint32_t a0[4], a1[4];
                ldsm_x4(a0[0], a0[1], a0[2], a0[3], stA0 + off);
                ldsm_x4(a1[0], a1[1], a1[2], a1[3], stA1 + off);
#pragma unroll
                for (int in_ = 0; in_ < NT; in_++) {
                    mma_s8(accP[im][in_], a0, b0[in_]);
                    mma_s8(accQ[im][in_], a0, b1[in_]);
                    mma_s8(accQ[im][in_], a1, b0[in_]);
                }
            }
        }
        __syncthreads();
    }

    float lsum = 0.f, lsq = 0.f;
#pragma unroll
    for (int im = 0; im < MT; im++) {
#pragma unroll
        for (int h2 = 0; h2 < 2; h2++) {
            const int row = m0 + warp_m * WM + im * 16 + qr + h2 * 8;
            const float sa = sA[row];
#pragma unroll
            for (int in_ = 0; in_ < NT; in_++) {
                const int col = n0 + warp_n * WN + in_ * 8 + qc * 2;
                float P0 = (float)accP[im][in_][h2 * 2 + 0];
                float P1 = (float)accP[im][in_][h2 * 2 + 1];
                float Q0 = (float)accQ[im][in_][h2 * 2 + 0];
                float Q1 = (float)accQ[im][in_][h2 * 2 + 1];
                float v0 = sa * sB[col]     * (P0 + Q0 * 0.00390625f) + bias[col];
                float v1 = sa * sB[col + 1] * (P1 + Q1 * 0.00390625f) + bias[col + 1];
                if (RELU) { v0 = fmaxf(v0, 0.f); v1 = fmaxf(v1, 0.f); }
                if (LN) {
                    float2 s2 = *reinterpret_cast<const float2*>(&src[(long)row * ldc + col]);
                    v0 += s2.x; v1 += s2.y;
                    lsum += v0 + v1;
                    lsq  += v0 * v0 + v1 * v1;
                }
                float2 o; o.x = v0; o.y = v1;
                *reinterpret_cast<float2*>(&C[(long)row * ldc + col]) = o;
            }
        }
    }

    if (LN) {
        s_red0[tid] = lsum; s_red1[tid] = lsq;
        __syncthreads();
        for (int s = 128; s > 0; s >>= 1) {
            if (tid < s) { s_red0[tid] += s_red0[tid + s]; s_red1[tid] += s_red1[tid + s]; }
            __syncthreads();
        }
        if (tid == 0) {
            int cta = blockIdx.y * gridDim.x + blockIdx.x;
            psum[cta] = s_red0[0];
            psq [cta] = s_red1[0];
        }
    }
}

// ---------------------------------------------------------------------------
// Per-row 2-limb int8 quantization: v = s*(q0 + q1/256), s = rowmax/127
// ---------------------------------------------------------------------------
template<int C>
__global__ void __launch_bounds__(256)
quant_rows(const float* __restrict__ in, s8* __restrict__ q0, s8* __restrict__ q1,
           float* __restrict__ s)
{
    const long row = blockIdx.x;
    const float* p = in + row * C;
    __shared__ float red[256];
    int t = threadIdx.x;
    float mx = 0.f;
    for (int i = t * 4; i < C; i += 1024) {
        float4 v = *reinterpret_cast<const float4*>(&p[i]);
        mx = fmaxf(mx, fmaxf(fmaxf(fabsf(v.x), fabsf(v.y)), fmaxf(fabsf(v.z), fabsf(v.w))));
    }
    red[t] = mx; __syncthreads();
    for (int st = 128; st > 0; st >>= 1) {
        if (t < st) red[t] = fmaxf(red[t], red[t + st]);
        __syncthreads();
    }
    float rmax = red[0];
    float sc  = (rmax > 0.f) ? rmax * (1.0f / 127.0f) : 1.0f;
    float inv = 1.0f / sc;
    if (t == 0) s[row] = sc;
    for (int i = t * 4; i < C; i += 1024) {
        float4 v = *reinterpret_cast<const float4*>(&p[i]);
        float a[4] = { v.x * inv, v.y * inv, v.z * inv, v.w * inv };
        uint32_t p0 = 0, p1 = 0;
#pragma unroll
        for (int u = 0; u < 4; u++) {
            int i0 = (int)rintf(a[u]);
            i0 = min(127, max(-127, i0));
            float r = (a[u] - (float)i0) * 256.0f;
            int i1 = (int)rintf(r);
            i1 = min(127, max(-127, i1));
            p0 |= ((uint32_t)(i0 & 255)) << (u * 8);
            p1 |= ((uint32_t)(i1 & 255)) << (u * 8);
        }
        *reinterpret_cast<uint32_t*>(&q0[row * C + i]) = p0;
        *reinterpret_cast<uint32_t*>(&q1[row * C + i]) = p1;
    }
}

// ---------------------------------------------------------------------------
// rowsum reciprocal
// ---------------------------------------------------------------------------
__global__ void rinv_kernel(const float* __restrict__ rpart, float* __restrict__ rinv) {
    int r = blockIdx.x * 256 + threadIdx.x;
    if (r >= MSROWS) return;
    float s = 0.f;
#pragma unroll
    for (int j = 0; j < 16; j++) s += rpart[r * 16 + j];
    rinv[r] = 1.0f / s;
}

// ---------------------------------------------------------------------------
// Transposes / weight prep
// ---------------------------------------------------------------------------
__global__ void transpose_b16(const bf16* __restrict__ in, bf16* __restrict__ out,
                              int ldin, long inB, long outB, int R, int C_) {
    __shared__ bf16 tt[32][33];
    const bf16* ip = in + blockIdx.z * inB;
    bf16* op = out + blockIdx.z * outB;
    int r0 = blockIdx.y * 32, c0 = blockIdx.x * 32;
#pragma unroll
    for (int i = 0; i < 32; i += 8)
        tt[threadIdx.y + i][threadIdx.x] = ip[(long)(r0 + threadIdx.y + i) * ldin + c0 + threadIdx.x];
    __syncthreads();
#pragma unroll
    for (int i = 0; i < 32; i += 8)
        op[(long)(c0 + threadIdx.y + i) * R + r0 + threadIdx.x] = tt[threadIdx.x][threadIdx.y + i];
}

__global__ void transpose_f32(const float* __restrict__ in, float* __restrict__ out,
                              int R, int C_) {
    __shared__ float tt[32][33];
    int r0 = blockIdx.y * 32, c0 = blockIdx.x * 32;
#pragma unroll
    for (int i = 0; i < 32; i += 8)
        tt[threadIdx.y + i][threadIdx.x] = in[(long)(r0 + threadIdx.y + i) * C_ + c0 + threadIdx.x];
    __syncthreads();
#pragma unroll
    for (int i = 0; i < 32; i += 8)
        out[(long)(c0 + threadIdx.y + i) * R + r0 + threadIdx.x] = tt[threadIdx.x][threadIdx.y + i];
}

__global__ void prep_qkvw(const float* __restrict__ Wq, const float* __restrict__ Wk,
                          const float* __restrict__ Wv, const float* __restrict__ bq,
                          const float* __restrict__ bk, const float* __restrict__ bv) {
    int idx = blockIdx.x * 256 + threadIdx.x;
    if (idx < 192 * DD) {
        int n = idx >> 9, k = idx & 511;
        const float* W = (n < 64) ? Wq : ((n < 128) ? Wk : Wv);
        float v = W[k * DKK + (n & 63)];
        split1(v, g_wqkvTh[idx], g_wqkvTl[idx]);
    }
    if (idx < 192) {
        g_bqkv[idx] = (idx < 64) ? bq[idx] : ((idx < 128) ? bk[idx - 64] : bv[idx - 128]);
    }
}

__global__ void prep_wo(const float* __restrict__ Wo) {
    int idx = blockIdx.x * 256 + threadIdx.x;
    if (idx >= DD * DKK) return;
    int e = idx / DKK, t = idx % DKK;
    float s = 0.f;
#pragma unroll
    for (int j = 0; j < 8; j++) s += Wo[(j * DKK + t) * DD + e];
    split1(s, g_woTh[idx], g_woTl[idx]);
}

// ---------------------------------------------------------------------------
// Embedding + positional encoding
// ---------------------------------------------------------------------------
__global__ void embed_kernel(const int* __restrict__ ids, const float* __restrict__ emb) {
    long i2 = (long)blockIdx.x * 256 + threadIdx.x;
    if (i2 >= NTOT / 2) return;
    long e = i2 * 2;
    int d  = (int)(e & (DD - 1));
    int bs = (int)(e >> 9);
    int s  = bs & (SS - 1);
    int id = ids[bs];
    float v0 = 0.f, v1 = 0.f;
    if (id != 0) {
        const float* er = emb + (long)id * DD;
        v0 = er[d]; v1 = er[d + 1];
    }
    double f0 = pow(10000.0, (double)d / 256.0);
    double f1 = pow(10000.0, (double)(d + 1) / 256.0);
    v0 += sinf((float)((double)s / f0));
    v1 += cosf((float)((double)s / f1));
    float2 o; o.x = v0; o.y = v1;
    *reinterpret_cast<float2*>(&g_x[e]) = o;
    uint32_t hp, lp;
    split_bf16(v0, v1, hp, lp);
    *reinterpret_cast<uint32_t*>(&g_xh[e]) = hp;
    *reinterpret_cast<uint32_t*>(&g_xl[e]) = lp;
}

// ---------------------------------------------------------------------------
// LayerNorm finalize + normalize
// ---------------------------------------------------------------------------
__global__ void finalize_kernel(int n) {
    __shared__ double ds[256], dq[256];
    double a = 0.0, b = 0.0;
    for (int i = threadIdx.x; i < n; i += 256) {
        a += (double)g_psum[i];
        b += (double)g_psq[i];
    }
    ds[threadIdx.x] = a; dq[threadIdx.x] = b; __syncthreads();
    for (int s = 128; s > 0; s >>= 1) {
        if (threadIdx.x < s) {
            ds[threadIdx.x] += ds[threadIdx.x + s];
            dq[threadIdx.x] += dq[threadIdx.x + s];
        }
        __syncthreads();
    }
    if (threadIdx.x == 0) {
        double m = ds[0] / (double)NTOT;
        double v = dq[0] / (double)NTOT - m * m;
        g_stats[0] = (float)m;
        g_stats[1] = (float)(1.0 / sqrt(v + 1e-5));
    }
}

__global__ void normalize_kernel(const float* __restrict__ y, float* __restrict__ out,
                                 bf16* __restrict__ oh, bf16* __restrict__ ol) {
    long i2 = (long)blockIdx.x * 256 + threadIdx.x;
    long e = i2 * 2;
    if (e >= NTOT) return;
    float m = g_stats[0], rs = g_stats[1];
    float2 yy = *reinterpret_cast<const float2*>(&y[e]);
    float v0 = (yy.x - m) * rs, v1 = (yy.y - m) * rs;
    float2 o; o.x = v0; o.y = v1;
    *reinterpret_cast<float2*>(&out[e]) = o;
    if (oh) {
        uint32_t hp, lp;
        split_bf16(v0, v1, hp, lp);
        *reinterpret_cast<uint32_t*>(&oh[e]) = hp;
        *reinterpret_cast<uint32_t*>(&ol[e]) = lp;
    }
}

// ---------------------------------------------------------------------------
// Launch
// ---------------------------------------------------------------------------
extern "C" void kernel_launch(void* const* d_in, const int* in_sizes, int n_in,
                              void* d_out, int out_size)
{
    const int*   ids = (const int*)  d_in[0];
    const float* emb = (const float*)d_in[1];
    const float* Wq  = (const float*)d_in[2];
    const float* bq  = (const float*)d_in[3];
    const float* Wk  = (const float*)d_in[4];
    const float* bk  = (const float*)d_in[5];
    const float* Wv  = (const float*)d_in[6];
    const float* bv  = (const float*)d_in[7];
    const float* Wo  = (const float*)d_in[8];
    const float* bo  = (const float*)d_in[9];
    const float* W1  = (const float*)d_in[10];
    const float* b1  = (const float*)d_in[11];
    const float* W2  = (const float*)d_in[12];
    const float* b2  = (const float*)d_in[13];

    float *x, *x1, *y, *h, *bqkv, *rpart, *rinv, *psum, *psq;
    float *sx1, *sh, *sw1, *sw2;
    bf16 *xh, *xl, *qkvh, *qkvl, *vTh, *vTl, *headh, *headl, *probsh, *probsl;
    bf16 *wqkvTh, *wqkvTl, *woTh, *woTl;
    s8 *x1q0, *x1q1, *hq0, *hq1, *w1q0, *w1q1, *w2q0, *w2q1;
    cudaGetSymbolAddress((void**)&x,      g_x);
    cudaGetSymbolAddress((void**)&x1,     g_x1);
    cudaGetSymbolAddress((void**)&y,      g_y);
    cudaGetSymbolAddress((void**)&h,      g_h);
    cudaGetSymbolAddress((void**)&xh,     g_xh);
    cudaGetSymbolAddress((void**)&xl,     g_xl);
    cudaGetSymbolAddress((void**)&qkvh,   g_qkvh);
    cudaGetSymbolAddress((void**)&qkvl,   g_qkvl);
    cudaGetSymbolAddress((void**)&vTh,    g_vTh);
    cudaGetSymbolAddress((void**)&vTl,    g_vTl);
    cudaGetSymbolAddress((void**)&headh,  g_headh);
    cudaGetSymbolAddress((void**)&headl,  g_headl);
    cudaGetSymbolAddress((void**)&probsh, g_probsh);
    cudaGetSymbolAddress((void**)&probsl, g_probsl);
    cudaGetSymbolAddress((void**)&wqkvTh, g_wqkvTh);
    cudaGetSymbolAddress((void**)&wqkvTl, g_wqkvTl);
    cudaGetSymbolAddress((void**)&woTh,   g_woTh);
    cudaGetSymbolAddress((void**)&woTl,   g_woTl);
    cudaGetSymbolAddress((void**)&bqkv,   g_bqkv);
    cudaGetSymbolAddress((void**)&rpart,  g_rpart);
    cudaGetSymbolAddress((void**)&rinv,   g_rinv);
    cudaGetSymbolAddress((void**)&psum,   g_psum);
    cudaGetSymbolAddress((void**)&psq,    g_psq);
    cudaGetSymbolAddress((void**)&x1q0,   g_x1q0);
    cudaGetSymbolAddress((void**)&x1q1,   g_x1q1);
    cudaGetSymbolAddress((void**)&sx1,    g_sx1);
    cudaGetSymbolAddress((void**)&hq0,    g_hq0);
    cudaGetSymbolAddress((void**)&hq1,    g_hq1);
    cudaGetSymbolAddress((void**)&sh,     g_sh);
    cudaGetSymbolAddress((void**)&w1q0,   g_w1q0);
    cudaGetSymbolAddress((void**)&w1q1,   g_w1q1);
    cudaGetSymbolAddress((void**)&sw1,    g_sw1);
    cudaGetSymbolAddress((void**)&w2q0,   g_w2q0);
    cudaGetSymbolAddress((void**)&w2q1,   g_w2q1);
    cudaGetSymbolAddress((void**)&sw2,    g_sw2);

    const int SM128 = 2 * (256 + 256) * SMSB * 2;   // bf16, 2 stages
    const int SM64  = 3 * (256 + 128) * SMSB * 2;   // bf16, 3 stages
    const int SMQ   = 3 * ((256 + 128) * SMSQ);     // int8, 3 stages = 92160

    cudaFuncSetAttribute((const void*)mma_gemm<64, 32, 32, 3, 1>,
                         cudaFuncAttributeMaxDynamicSharedMemorySize, SM64);
    cudaFuncSetAttribute((const void*)mma_gemm<64, 32, 32, 3, 3>,
                         cudaFuncAttributeMaxDynamicSharedMemorySize, SM64);
    cudaFuncSetAttribute((const void*)mma_gemm<128, 64, 32, 2, 2>,
                         cudaFuncAttributeMaxDynamicSharedMemorySize, SM128);
    cudaFuncSetAttribute((const void*)mma_gemm<128, 64, 32, 2, 0>,
                         cudaFuncAttributeMaxDynamicSharedMemorySize, SM128);
    cudaFuncSetAttribute((const void*)imma_gemm<true, false>,
                         cudaFuncAttributeMaxDynamicSharedMemorySize, SMQ);
    cudaFuncSetAttribute((const void*)imma_gemm<false, true>,
                         cudaFuncAttributeMaxDynamicSharedMemorySize, SMQ);

    const float inv_div = 1.0f / 32.0f;
    dim3 tb(32, 8);

    // ---- weight prep ----
    prep_qkvw<<<(192 * DD + 255) / 256, 256>>>(Wq, Wk, Wv, bq, bk, bv);
    prep_wo<<<(DD * DKK + 255) / 256, 256>>>(Wo);
    // W1^T -> h scratch -> quant; W2^T likewise
    transpose_f32<<<dim3(DFFN / 32, DD / 32), tb>>>(W1, h, DD, DFFN);
    quant_rows<DD><<<DFFN, 256>>>(h, w1q0, w1q1, sw1);
    transpose_f32<<<dim3(DD / 32, DFFN / 32), tb>>>(W2, h, DFFN, DD);
    quant_rows<DFFN><<<DD, 256>>>(h, w2q0, w2q1, sw2);

    embed_kernel<<<NTOT / 512, 256>>>(ids, emb);

    for (int it = 0; it < NREP; it++) {
        // QKV fused (bf16 3-term)
        mma_gemm<64, 32, 32, 3, 1><<<dim3(3, 128, 1), 256, SM64>>>(
            xh, xl, DD, 0, wqkvTh, wqkvTl, DD, 0, bqkv, 0,
            0, qkvh, qkvl, 192, 0, DD, 1.f, 0, 0, 0, 0);

        // probs(unnorm) = exp(q k^T / 32), row partials
        mma_gemm<128, 64, 32, 2, 2><<<dim3(16, 16, BB), 256, SM128>>>(
            qkvh, qkvl, 192, (long)SS * 192,
            qkvh + 64, qkvl + 64, 192, (long)SS * 192,
            0, 0, 0, probsh, probsl, SS, (long)SS * SS, DKK, inv_div,
            rpart, 0, 0, 0);

        rinv_kernel<<<MSROWS / 256, 256>>>(rpart, rinv);

        transpose_b16<<<dim3(2, 64, BB), tb>>>(qkvh + 128, vTh, 192,
                                               (long)SS * 192, (long)DKK * SS, SS, DKK);
        transpose_b16<<<dim3(2, 64, BB), tb>>>(qkvl + 128, vTl, 192,
                                               (long)SS * 192, (long)DKK * SS, SS, DKK);

        // head = (exp @ v) * rinv
        mma_gemm<64, 32, 32, 3, 3><<<dim3(1, 16, BB), 256, SM64>>>(
            probsh, probsl, SS, (long)SS * SS,
            vTh, vTl, SS, (long)DKK * SS,
            0, 0, 0, headh, headl, DKK, (long)SS * DKK, SS, 1.f,
            0, rinv, 0, 0);

        // y = head @ Wo_eff + bo + x, LN partials
        mma_gemm<128, 64, 32, 2, 0><<<dim3(4, 128, 1), 256, SM128>>>(
            headh, headl, DKK, 0, woTh, woTl, DKK, 0, bo, x,
            y, 0, 0, DD, 0, DKK, 1.f, 0, 0, psum, psq);

        finalize_kernel<<<1, 256>>>(512);
        normalize_kernel<<<NTOT / 512, 256>>>(y, x1, 0, 0);

        // quantize x1, FFN1 (int8): h = relu(x1 @ W1 + b1), fp32 out
        quant_rows<DD><<<MSROWS, 256>>>(x1, x1q0, x1q1, sx1);
        imma_gemm<true, false><<<dim3(DFFN / 64, 128, 1), 256, SMQ>>>(
            x1q0, x1q1, sx1, DD, w1q0, w1q1, sw1, DD, b1, 0,
            h, DFFN, DD, 0, 0);

        // quantize h, FFN2 (int8): y = h @ W2 + b2 + x1, LN partials
        quant_rows<DFFN><<<MSROWS, 256>>>(h, hq0, hq1, sh);
        imma_gemm<false, true><<<dim3(DD / 64, 128, 1), 256, SMQ>>>(
            hq0, hq1, sh, DFFN, w2q0, w2q1, sw2, DFFN, b2, x1,
            y, DD, DFFN, psum, psq);

        finalize_kernel<<<1, 256>>>(1024);
        if (it == NREP - 1)
            normalize_kernel<<<NTOT / 512, 256>>>(y, (float*)d_out, 0, 0);
        else
            normalize_kernel<<<NTOT / 512, 256>>>(y, x, xh, xl);
    }
}

// round 8
// speedup vs baseline: 1.8648x; 1.8648x over previous
#include <cuda_runtime.h>
#include <cuda_bf16.h>
#include <math.h>
#include <stdint.h>

#define BB   8
#define SS   2048
#define DD   512
#define DKK  64
#define DFFN 2048
#define NREP 6
#define MSROWS (BB*SS)          // 16384
#define NTOT (BB*SS*DD)         // 8388608

typedef __nv_bfloat16 bf16;

// ---------------------------------------------------------------------------
// Scratch
// ---------------------------------------------------------------------------
__device__ float g_y [NTOT];

__device__ bf16 g_xh [NTOT];
__device__ bf16 g_xl [NTOT];
__device__ bf16 g_x1h[NTOT];
__device__ bf16 g_x1l[NTOT];
__device__ bf16 g_qkvh[MSROWS*192];
__device__ bf16 g_qkvl[MSROWS*192];
__device__ bf16 g_headh[MSROWS*DKK];
__device__ bf16 g_headl[MSROWS*DKK];
__device__ bf16 g_hh[(long)MSROWS*DFFN];
__device__ bf16 g_hl[(long)MSROWS*DFFN];

__device__ bf16 g_wqkvTh[192*DD];
__device__ bf16 g_wqkvTl[192*DD];
__device__ bf16 g_woTh[DD*DKK];
__device__ bf16 g_woTl[DD*DKK];
__device__ bf16 g_w1Th[DFFN*DD];
__device__ bf16 g_w1Tl[DFFN*DD];
__device__ bf16 g_w2Th[DD*DFFN];
__device__ bf16 g_w2Tl[DD*DFFN];
__device__ float g_bqkv[192];

__device__ float g_psum[1024];
__device__ float g_psq [1024];
__device__ float g_stats[2];

// ---------------------------------------------------------------------------
// Helpers
// ---------------------------------------------------------------------------
__device__ __forceinline__ uint32_t cvta_shared_u32(const void* p) {
    uint32_t a;
    asm("{ .reg .u64 t; cvta.to.shared.u64 t, %1; cvt.u32.u64 %0, t; }" : "=r"(a) : "l"(p));
    return a;
}
__device__ __forceinline__ void cp_async16(uint32_t saddr, const void* gptr) {
    asm volatile("cp.async.cg.shared.global [%0], [%1], 16;" :: "r"(saddr), "l"(gptr));
}
__device__ __forceinline__ void cp_commit() {
    asm volatile("cp.async.commit_group;" ::: "memory");
}
template<int N>
__device__ __forceinline__ void cp_wait() {
    asm volatile("cp.async.wait_group %0;" :: "n"(N) : "memory");
}
__device__ __forceinline__ void ldsm_x4(uint32_t& r0, uint32_t& r1, uint32_t& r2, uint32_t& r3,
                                        uint32_t addr) {
    asm volatile("ldmatrix.sync.aligned.m8n8.x4.shared.b16 {%0,%1,%2,%3}, [%4];"
                 : "=r"(r0), "=r"(r1), "=r"(r2), "=r"(r3) : "r"(addr));
}
__device__ __forceinline__ void ldsm_x4_t(uint32_t& r0, uint32_t& r1, uint32_t& r2, uint32_t& r3,
                                          uint32_t addr) {
    asm volatile("ldmatrix.sync.aligned.m8n8.x4.trans.shared.b16 {%0,%1,%2,%3}, [%4];"
                 : "=r"(r0), "=r"(r1), "=r"(r2), "=r"(r3) : "r"(addr));
}
__device__ __forceinline__ void split_bf16(float e0, float e1, uint32_t& hi, uint32_t& lo) {
    asm("cvt.rn.bf16x2.f32 %0, %1, %2;" : "=r"(hi) : "f"(e1), "f"(e0));
    float h0 = __uint_as_float(hi << 16);
    float h1 = __uint_as_float(hi & 0xffff0000u);
    float l0 = e0 - h0;
    float l1 = e1 - h1;
    asm("cvt.rn.bf16x2.f32 %0, %1, %2;" : "=r"(lo) : "f"(l1), "f"(l0));
}
__device__ __forceinline__ void split1(float v, bf16& h, bf16& l) {
    h = __float2bfloat16_rn(v);
    l = __float2bfloat16_rn(v - __bfloat162float(h));
}
__device__ __forceinline__ void mma_bf16(float* c, const uint32_t* a, const uint32_t* b) {
    asm volatile(
        "mma.sync.aligned.m16n8k16.row.col.f32.bf16.bf16.f32 "
        "{%0,%1,%2,%3}, {%4,%5,%6,%7}, {%8,%9}, {%0,%1,%2,%3};"
        : "+f"(c[0]), "+f"(c[1]), "+f"(c[2]), "+f"(c[3])
        : "r"(a[0]), "r"(a[1]), "r"(a[2]), "r"(a[3]), "r"(b[0]), "r"(b[1]));
}

// ---------------------------------------------------------------------------
// bf16 pre-split GEMM. Modes:
// 0: C fp32 = acc*alpha + bias + (srch+srcl), + LN partials (psum/psq per CTA)
// 1: Chi/Clo = split(acc*alpha + bias) [optional RELU]
// ---------------------------------------------------------------------------
#define SMSB 40

template<int BN, int WM, int WN, int STAGES, int MODE, bool RELU>
__global__ void __launch_bounds__(256, 2)
mma_gemm(const bf16* __restrict__ Ahi, const bf16* __restrict__ Alo, int lda,
         const bf16* __restrict__ Bhi, const bf16* __restrict__ Blo, int ldb,
         const float* __restrict__ bias,
         const bf16* __restrict__ srch, const bf16* __restrict__ srcl,
         float* __restrict__ C, bf16* __restrict__ Chi, bf16* __restrict__ Clo,
         int ldc, int K, float alpha,
         float* __restrict__ psum, float* __restrict__ psq)
{
    constexpr int MT = WM / 16;
    constexpr int NT = WN / 8;
    constexpr int WARPS_N = BN / WN;
    static_assert((128 / WM) * (BN / WN) == 8, "8 warps");
    static_assert(NT % 2 == 0, "NT even");

    constexpr int OFF_ALO = 128 * SMSB;
    constexpr int OFF_BHI = 256 * SMSB;
    constexpr int OFF_BLO = OFF_BHI + BN * SMSB;
    constexpr int BUFSZ   = OFF_BLO + BN * SMSB;

    extern __shared__ bf16 smem[];
    __shared__ float s_red0[256];
    __shared__ float s_red1[256];

    const int tid  = threadIdx.x;
    const int lane = tid & 31;
    const int wid  = tid >> 5;
    const int warp_m = wid / WARPS_N;
    const int warp_n = wid % WARPS_N;
    const int qr = lane >> 2;
    const int qc = lane & 3;

    const int m0 = blockIdx.y * 128;
    const int n0 = blockIdx.x * BN;

    float acc[MT][NT][4];
#pragma unroll
    for (int i = 0; i < MT; i++)
#pragma unroll
        for (int j = 0; j < NT; j++)
#pragma unroll
            for (int u = 0; u < 4; u++) acc[i][j][u] = 0.f;

    const uint32_t sb = cvta_shared_u32(smem);

    auto load_chunk = [&](int c, int stg) {
        const int k0 = c << 5;
        const uint32_t base = sb + (uint32_t)stg * (BUFSZ * 2);
#pragma unroll
        for (int i = 0; i < 2; i++) {
            int idx = tid + i * 256;
            int row = idx >> 2, c8 = idx & 3;
            long g = (long)(m0 + row) * lda + k0 + c8 * 8;
            uint32_t so = (uint32_t)(row * SMSB + c8 * 8) * 2;
            cp_async16(base + so, Ahi + g);
            cp_async16(base + OFF_ALO * 2 + so, Alo + g);
        }
#pragma unroll
        for (int i = 0; i < BN / 64; i++) {
            int idx = tid + i * 256;
            int row = idx >> 2, c8 = idx & 3;
            long g = (long)(n0 + row) * ldb + k0 + c8 * 8;
            uint32_t so = (uint32_t)(row * SMSB + c8 * 8) * 2;
            cp_async16(base + OFF_BHI * 2 + so, Bhi + g);
            cp_async16(base + OFF_BLO * 2 + so, Blo + g);
        }
    };

    const int nch = K >> 5;
#pragma unroll
    for (int s = 0; s < STAGES - 1; s++) { load_chunk(s, s); cp_commit(); }

    const uint32_t a_off = (uint32_t)(((lane & 15) + warp_m * WM) * SMSB + (lane >> 4) * 8) * 2;
    const uint32_t b_off = (uint32_t)((((lane >> 4) & 1) * 8 + (lane & 7) + warp_n * WN) * SMSB
                                      + ((lane >> 3) & 1) * 8) * 2;

    for (int c = 0; c < nch; c++) {
        const int stg = c % STAGES;
        if (c + STAGES - 1 < nch) {
            load_chunk(c + STAGES - 1, (c + STAGES - 1) % STAGES);
            cp_commit();
            cp_wait<STAGES - 1>();
        } else {
            cp_wait<0>();
        }
        __syncthreads();

        const uint32_t stA  = sb + (uint32_t)stg * (BUFSZ * 2);
        const uint32_t stAl = stA + OFF_ALO * 2;
        const uint32_t stBh = stA + OFF_BHI * 2;
        const uint32_t stBl = stA + OFF_BLO * 2;

#pragma unroll
        for (int ks = 0; ks < 2; ks++) {
            const uint32_t kk2 = (uint32_t)ks * 32;
            uint32_t bh[NT][2], bl[NT][2];
#pragma unroll
            for (int in2 = 0; in2 < NT / 2; in2++) {
                uint32_t off = b_off + (uint32_t)in2 * (16 * SMSB * 2) + kk2;
                ldsm_x4(bh[2*in2][0], bh[2*in2][1], bh[2*in2+1][0], bh[2*in2+1][1], stBh + off);
                ldsm_x4(bl[2*in2][0], bl[2*in2][1], bl[2*in2+1][0], bl[2*in2+1][1], stBl + off);
            }
#pragma unroll
            for (int im = 0; im < MT; im++) {
                uint32_t off = a_off + (uint32_t)im * (16 * SMSB * 2) + kk2;
                uint32_t ah[4], al[4];
                ldsm_x4(ah[0], ah[1], ah[2], ah[3], stA + off);
                ldsm_x4(al[0], al[1], al[2], al[3], stAl + off);
#pragma unroll
                for (int in_ = 0; in_ < NT; in_++) {
                    mma_bf16(acc[im][in_], ah, bh[in_]);
                    mma_bf16(acc[im][in_], al, bh[in_]);
                    mma_bf16(acc[im][in_], ah, bl[in_]);
                }
            }
        }
        __syncthreads();
    }

    float lsum = 0.f, lsq = 0.f;
#pragma unroll
    for (int im = 0; im < MT; im++) {
#pragma unroll
        for (int h2 = 0; h2 < 2; h2++) {
            const int row = m0 + warp_m * WM + im * 16 + qr + h2 * 8;
#pragma unroll
            for (int in_ = 0; in_ < NT; in_++) {
                const int col = n0 + warp_n * WN + in_ * 8 + qc * 2;
                float v0 = acc[im][in_][h2 * 2 + 0] * alpha;
                float v1 = acc[im][in_][h2 * 2 + 1] * alpha;
                if (bias) { v0 += bias[col]; v1 += bias[col + 1]; }
                if (MODE == 0) {
                    long si = (long)row * ldc + col;
                    v0 += __bfloat162float(srch[si])     + __bfloat162float(srcl[si]);
                    v1 += __bfloat162float(srch[si + 1]) + __bfloat162float(srcl[si + 1]);
                    float2 o; o.x = v0; o.y = v1;
                    *reinterpret_cast<float2*>(&C[(long)row * ldc + col]) = o;
                    lsum += v0 + v1;
                    lsq  += v0 * v0 + v1 * v1;
                } else {
                    if (RELU) { v0 = fmaxf(v0, 0.f); v1 = fmaxf(v1, 0.f); }
                    uint32_t hp, lp;
                    split_bf16(v0, v1, hp, lp);
                    *reinterpret_cast<uint32_t*>(&Chi[(long)row * ldc + col]) = hp;
                    *reinterpret_cast<uint32_t*>(&Clo[(long)row * ldc + col]) = lp;
                }
            }
        }
    }

    if (MODE == 0) {
        s_red0[tid] = lsum; s_red1[tid] = lsq;
        __syncthreads();
        for (int s = 128; s > 0; s >>= 1) {
            if (tid < s) { s_red0[tid] += s_red0[tid + s]; s_red1[tid] += s_red1[tid + s]; }
            __syncthreads();
        }
        if (tid == 0) {
            int cta = blockIdx.y * gridDim.x + blockIdx.x;
            psum[cta] = s_red0[0];
            psq [cta] = s_red1[0];
        }
    }
}

// ---------------------------------------------------------------------------
// Flash attention: head = softmax(q k^T * alpha) @ v, fp32-accurate via
// 3-term bf16 splits. One CTA = 128 q rows; 8 warps x 16 rows.
// K/V chunks of 64 keys double-buffered; P kept in registers (C-frag -> A-frag).
// ---------------------------------------------------------------------------
#define FAS 72   // smem row stride in bf16 elems (64 + 8 pad)

__global__ void __launch_bounds__(256)
flash_attn(const bf16* __restrict__ qkvh, const bf16* __restrict__ qkvl,
           bf16* __restrict__ headh, bf16* __restrict__ headl, float alpha)
{
    constexpr int QSZ = 128 * FAS;   // elems
    constexpr int CSZ = 64 * FAS;

    extern __shared__ bf16 fsm[];
    const uint32_t sb = cvta_shared_u32(fsm);
    const uint32_t qh_a = sb;
    const uint32_t ql_a = sb + QSZ * 2;
    const uint32_t ck_a = sb + 2 * QSZ * 2;   // 8 chunk tensors (2 bufs x {kh,kl,vh,vl})

    const int tid  = threadIdx.x;
    const int lane = tid & 31;
    const int wid  = tid >> 5;
    const int qr = lane >> 2, qc = lane & 3;
    const long bz = blockIdx.y;
    const long grow0 = bz * SS + blockIdx.x * 128;

    // ---- load Q tile (128 x 64, hi+lo) ----
#pragma unroll
    for (int i = 0; i < 4; i++) {
        int idx = tid + i * 256;
        int r = idx >> 3, s = idx & 7;
        long g = (grow0 + r) * 192 + s * 8;
        uint32_t so = (uint32_t)(r * FAS + s * 8) * 2;
        cp_async16(qh_a + so, qkvh + g);
        cp_async16(ql_a + so, qkvl + g);
    }
    cp_commit();

    auto load_chunk = [&](int c, int buf) {
        const uint32_t base = ck_a + (uint32_t)buf * 4 * CSZ * 2;
#pragma unroll
        for (int i = 0; i < 2; i++) {
            int idx = tid + i * 256;
            int r = idx >> 3, s = idx & 7;
            long g = (bz * SS + c * 64 + r) * 192 + s * 8;
            uint32_t so = (uint32_t)(r * FAS + s * 8) * 2;
            cp_async16(base + so,               qkvh + g + 64);    // k hi
            cp_async16(base + CSZ * 2 + so,     qkvl + g + 64);    // k lo
            cp_async16(base + 2 * CSZ * 2 + so, qkvh + g + 128);   // v hi
            cp_async16(base + 3 * CSZ * 2 + so, qkvl + g + 128);   // v lo
        }
        cp_commit();
    };

    load_chunk(0, 0);

    // wait for Q (1 group may remain outstanding: chunk 0)
    cp_wait<1>();
    __syncthreads();

    // ---- preload Q fragments (4 ksteps x a[4], hi+lo) ----
    const uint32_t qa_off = (uint32_t)((lane & 15) + wid * 16) * (FAS * 2) + (lane >> 4) * 16;
    uint32_t qah[4][4], qal[4][4];
#pragma unroll
    for (int ks = 0; ks < 4; ks++) {
        ldsm_x4(qah[ks][0], qah[ks][1], qah[ks][2], qah[ks][3], qh_a + qa_off + ks * 32);
        ldsm_x4(qal[ks][0], qal[ks][1], qal[ks][2], qal[ks][3], ql_a + qa_off + ks * 32);
    }

    const uint32_t kb_off = (uint32_t)((((lane >> 4) & 1) * 8 + (lane & 7)) * FAS) * 2
                            + ((lane >> 3) & 1) * 16;
    const uint32_t vb_off = (uint32_t)(((lane & 7) + ((lane >> 3) & 1) * 8) * FAS) * 2
                            + ((lane >> 4) & 1) * 16;

    float o[8][4];
#pragma unroll
    for (int t = 0; t < 8; t++)
#pragma unroll
        for (int u = 0; u < 4; u++) o[t][u] = 0.f;
    float rs0 = 0.f, rs1 = 0.f;

    for (int c = 0; c < SS / 64; c++) {
        const int buf = c & 1;
        cp_wait<0>();
        __syncthreads();
        if (c + 1 < SS / 64) load_chunk(c + 1, buf ^ 1);

        const uint32_t kh_a = ck_a + (uint32_t)buf * 4 * CSZ * 2;
        const uint32_t kl_a = kh_a + CSZ * 2;
        const uint32_t vh_a = kh_a + 2 * CSZ * 2;
        const uint32_t vl_a = kh_a + 3 * CSZ * 2;

        // ---- S = q k^T  (8 key-tiles of n8) ----
        float s[8][4];
#pragma unroll
        for (int j = 0; j < 8; j++)
#pragma unroll
            for (int u = 0; u < 4; u++) s[j][u] = 0.f;

#pragma unroll
        for (int ks = 0; ks < 4; ks++) {
            uint32_t kbh[8][2], kbl[8][2];
#pragma unroll
            for (int j4 = 0; j4 < 4; j4++) {
                uint32_t off = kb_off + (uint32_t)j4 * (16 * FAS * 2) + ks * 32;
                ldsm_x4(kbh[2*j4][0], kbh[2*j4][1], kbh[2*j4+1][0], kbh[2*j4+1][1], kh_a + off);
                ldsm_x4(kbl[2*j4][0], kbl[2*j4][1], kbl[2*j4+1][0], kbl[2*j4+1][1], kl_a + off);
            }
#pragma unroll
            for (int j = 0; j < 8; j++) {
                mma_bf16(s[j], qah[ks], kbh[j]);
                mma_bf16(s[j], qal[ks], kbh[j]);
                mma_bf16(s[j], qah[ks], kbl[j]);
            }
        }

        // ---- P = exp(alpha*S); pack C-frags -> A-frags; row sums ----
        uint32_t pah[4][4], pal[4][4];
#pragma unroll
        for (int j = 0; j < 8; j++) {
            float p0 = __expf(s[j][0] * alpha);
            float p1 = __expf(s[j][1] * alpha);
            float p2 = __expf(s[j][2] * alpha);
            float p3 = __expf(s[j][3] * alpha);
            rs0 += p0 + p1;
            rs1 += p2 + p3;
            int ks = j >> 1, half = (j & 1) * 2;
            split_bf16(p0, p1, pah[ks][half + 0], pal[ks][half + 0]);
            split_bf16(p2, p3, pah[ks][half + 1], pal[ks][half + 1]);
        }
        // NOTE: a-frag order is {a0,a1,a2,a3} = {row qr k-lo, row qr+8 k-lo,
        // row qr k-hi, row qr+8 k-hi}; mapping above: even j -> slots 0,1; odd j -> 2,3. OK.

        // ---- O += P V ----
#pragma unroll
        for (int ks = 0; ks < 4; ks++) {
            uint32_t vbh[8][2], vbl[8][2];
#pragma unroll
            for (int i = 0; i < 4; i++) {
                uint32_t off = vb_off + (uint32_t)ks * (16 * FAS * 2) + i * 32;
                ldsm_x4_t(vbh[2*i][0], vbh[2*i][1], vbh[2*i+1][0], vbh[2*i+1][1], vh_a + off);
                ldsm_x4_t(vbl[2*i][0], vbl[2*i][1], vbl[2*i+1][0], vbl[2*i+1][1], vl_a + off);
            }
#pragma unroll
            for (int t = 0; t < 8; t++) {
                mma_bf16(o[t], pah[ks], vbh[t]);
                mma_bf16(o[t], pal[ks], vbh[t]);
                mma_bf16(o[t], pah[ks], vbl[t]);
            }
        }
    }

    // ---- epilogue: scale by 1/Z, split, store ----
    rs0 += __shfl_xor_sync(0xffffffffu, rs0, 1);
    rs0 += __shfl_xor_sync(0xffffffffu, rs0, 2);
    rs1 += __shfl_xor_sync(0xffffffffu, rs1, 1);
    rs1 += __shfl_xor_sync(0xffffffffu, rs1, 2);
    float inv0 = 1.0f / rs0;
    float inv1 = 1.0f / rs1;

    long g0 = grow0 + wid * 16 + qr;
#pragma unroll
    for (int t = 0; t < 8; t++) {
        int col = t * 8 + qc * 2;
        uint32_t hp, lp;
        split_bf16(o[t][0] * inv0, o[t][1] * inv0, hp, lp);
        *reinterpret_cast<uint32_t*>(&headh[g0 * DKK + col]) = hp;
        *reinterpret_cast<uint32_t*>(&headl[g0 * DKK + col]) = lp;
        split_bf16(o[t][2] * inv1, o[t][3] * inv1, hp, lp);
        *reinterpret_cast<uint32_t*>(&headh[(g0 + 8) * DKK + col]) = hp;
        *reinterpret_cast<uint32_t*>(&headl[(g0 + 8) * DKK + col]) = lp;
    }
}

// ---------------------------------------------------------------------------
// Weight prep
// ---------------------------------------------------------------------------
__global__ void transpose_split_f32(const float* __restrict__ in,
                                    bf16* __restrict__ oh, bf16* __restrict__ ol,
                                    int R, int C_) {
    __shared__ float tt[32][33];
    int r0 = blockIdx.y * 32, c0 = blockIdx.x * 32;
#pragma unroll
    for (int i = 0; i < 32; i += 8)
        tt[threadIdx.y + i][threadIdx.x] = in[(long)(r0 + threadIdx.y + i) * C_ + c0 + threadIdx.x];
    __syncthreads();
#pragma unroll
    for (int i = 0; i < 32; i += 8) {
        long o = (long)(c0 + threadIdx.y + i) * R + r0 + threadIdx.x;
        bf16 h, l;
        split1(tt[threadIdx.x][threadIdx.y + i], h, l);
        oh[o] = h; ol[o] = l;
    }
}

__global__ void prep_qkvw(const float* __restrict__ Wq, const float* __restrict__ Wk,
                          const float* __restrict__ Wv, const float* __restrict__ bq,
                          const float* __restrict__ bk, const float* __restrict__ bv) {
    int idx = blockIdx.x * 256 + threadIdx.x;
    if (idx < 192 * DD) {
        int n = idx >> 9, k = idx & 511;
        const float* W = (n < 64) ? Wq : ((n < 128) ? Wk : Wv);
        float v = W[k * DKK + (n & 63)];
        split1(v, g_wqkvTh[idx], g_wqkvTl[idx]);
    }
    if (idx < 192) {
        g_bqkv[idx] = (idx < 64) ? bq[idx] : ((idx < 128) ? bk[idx - 64] : bv[idx - 128]);
    }
}

__global__ void prep_wo(const float* __restrict__ Wo) {
    int idx = blockIdx.x * 256 + threadIdx.x;
    if (idx >= DD * DKK) return;
    int e = idx / DKK, t = idx % DKK;
    float s = 0.f;
#pragma unroll
    for (int j = 0; j < 8; j++) s += Wo[(j * DKK + t) * DD + e];
    split1(s, g_woTh[idx], g_woTl[idx]);
}

// ---------------------------------------------------------------------------
// Embedding + positional encoding (bf16 hi/lo only)
// ---------------------------------------------------------------------------
__global__ void embed_kernel(const int* __restrict__ ids, const float* __restrict__ emb) {
    long i2 = (long)blockIdx.x * 256 + threadIdx.x;
    if (i2 >= NTOT / 2) return;
    long e = i2 * 2;
    int d  = (int)(e & (DD - 1));
    int bs = (int)(e >> 9);
    int s  = bs & (SS - 1);
    int id = ids[bs];
    float v0 = 0.f, v1 = 0.f;
    if (id != 0) {
        const float* er = emb + (long)id * DD;
        v0 = er[d]; v1 = er[d + 1];
    }
    double f0 = pow(10000.0, (double)d / 256.0);
    double f1 = pow(10000.0, (double)(d + 1) / 256.0);
    v0 += sinf((float)((double)s / f0));
    v1 += cosf((float)((double)s / f1));
    uint32_t hp, lp;
    split_bf16(v0, v1, hp, lp);
    *reinterpret_cast<uint32_t*>(&g_xh[e]) = hp;
    *reinterpret_cast<uint32_t*>(&g_xl[e]) = lp;
}

// ---------------------------------------------------------------------------
// LayerNorm finalize + normalize
// ---------------------------------------------------------------------------
__global__ void finalize_kernel(int n) {
    __shared__ double ds[256], dq[256];
    double a = 0.0, b = 0.0;
    for (int i = threadIdx.x; i < n; i += 256) {
        a += (double)g_psum[i];
        b += (double)g_psq[i];
    }
    ds[threadIdx.x] = a; dq[threadIdx.x] = b; __syncthreads();
    for (int s = 128; s > 0; s >>= 1) {
        if (threadIdx.x < s) {
            ds[threadIdx.x] += ds[threadIdx.x + s];
            dq[threadIdx.x] += dq[threadIdx.x + s];
        }
        __syncthreads();
    }
    if (threadIdx.x == 0) {
        double m = ds[0] / (double)NTOT;
        double v = dq[0] / (double)NTOT - m * m;
        g_stats[0] = (float)m;
        g_stats[1] = (float)(1.0 / sqrt(v + 1e-5));
    }
}

__global__ void normalize_kernel(const float* __restrict__ y, float* __restrict__ out,
                                 bf16* __restrict__ oh, bf16* __restrict__ ol) {
    long i2 = (long)blockIdx.x * 256 + threadIdx.x;
    long e = i2 * 2;
    if (e >= NTOT) return;
    float m = g_stats[0], rs = g_stats[1];
    float2 yy = *reinterpret_cast<const float2*>(&y[e]);
    float v0 = (yy.x - m) * rs, v1 = (yy.y - m) * rs;
    if (out) {
        float2 o; o.x = v0; o.y = v1;
        *reinterpret_cast<float2*>(&out[e]) = o;
    }
    if (oh) {
        uint32_t hp, lp;
        split_bf16(v0, v1, hp, lp);
        *reinterpret_cast<uint32_t*>(&oh[e]) = hp;
        *reinterpret_cast<uint32_t*>(&ol[e]) = lp;
    }
}

// ---------------------------------------------------------------------------
// Launch
// ---------------------------------------------------------------------------
extern "C" void kernel_launch(void* const* d_in, const int* in_sizes, int n_in,
                              void* d_out, int out_size)
{
    const int*   ids = (const int*)  d_in[0];
    const float* emb = (const float*)d_in[1];
    const float* Wq  = (const float*)d_in[2];
    const float* bq  = (const float*)d_in[3];
    const float* Wk  = (const float*)d_in[4];
    const float* bk  = (const float*)d_in[5];
    const float* Wv  = (const float*)d_in[6];
    const float* bv  = (const float*)d_in[7];
    const float* Wo  = (const float*)d_in[8];
    const float* bo  = (const float*)d_in[9];
    const float* W1  = (const float*)d_in[10];
    const float* b1  = (const float*)d_in[11];
    const float* W2  = (const float*)d_in[12];
    const float* b2  = (const float*)d_in[13];

    float *y, *bqkv, *psum, *psq;
    bf16 *xh, *xl, *x1h, *x1l, *qkvh, *qkvl, *headh, *headl, *hh, *hl;
    bf16 *wqkvTh, *wqkvTl, *woTh, *woTl, *w1Th, *w1Tl, *w2Th, *w2Tl;
    cudaGetSymbolAddress((void**)&y,      g_y);
    cudaGetSymbolAddress((void**)&xh,     g_xh);
    cudaGetSymbolAddress((void**)&xl,     g_xl);
    cudaGetSymbolAddress((void**)&x1h,    g_x1h);
    cudaGetSymbolAddress((void**)&x1l,    g_x1l);
    cudaGetSymbolAddress((void**)&qkvh,   g_qkvh);
    cudaGetSymbolAddress((void**)&qkvl,   g_qkvl);
    cudaGetSymbolAddress((void**)&headh,  g_headh);
    cudaGetSymbolAddress((void**)&headl,  g_headl);
    cudaGetSymbolAddress((void**)&hh,     g_hh);
    cudaGetSymbolAddress((void**)&hl,     g_hl);
    cudaGetSymbolAddress((void**)&wqkvTh, g_wqkvTh);
    cudaGetSymbolAddress((void**)&wqkvTl, g_wqkvTl);
    cudaGetSymbolAddress((void**)&woTh,   g_woTh);
    cudaGetSymbolAddress((void**)&woTl,   g_woTl);
    cudaGetSymbolAddress((void**)&w1Th,   g_w1Th);
    cudaGetSymbolAddress((void**)&w1Tl,   g_w1Tl);
    cudaGetSymbolAddress((void**)&w2Th,   g_w2Th);
    cudaGetSymbolAddress((void**)&w2Tl,   g_w2Tl);
    cudaGetSymbolAddress((void**)&bqkv,   g_bqkv);
    cudaGetSymbolAddress((void**)&psum,   g_psum);
    cudaGetSymbolAddress((void**)&psq,    g_psq);

    const int SM128 = 2 * (256 + 256) * SMSB * 2;                 // 81920
    const int SM64  = 3 * (256 + 128) * SMSB * 2;                 // 92160
    const int SMFA  = (2 * 128 * FAS + 8 * 64 * FAS) * 2;         // 110592

    cudaFuncSetAttribute((const void*)mma_gemm<64, 32, 32, 3, 1, false>,
                         cudaFuncAttributeMaxDynamicSharedMemorySize, SM64);
    cudaFuncSetAttribute((const void*)mma_gemm<128, 64, 32, 2, 0, false>,
                         cudaFuncAttributeMaxDynamicSharedMemorySize, SM128);
    cudaFuncSetAttribute((const void*)mma_gemm<128, 64, 32, 2, 1, true>,
                         cudaFuncAttributeMaxDynamicSharedMemorySize, SM128);
    cudaFuncSetAttribute((const void*)flash_attn,
                         cudaFuncAttributeMaxDynamicSharedMemorySize, SMFA);

    const float inv_div = 1.0f / 32.0f;
    dim3 tb(32, 8);

    // ---- weight prep ----
    prep_qkvw<<<(192 * DD + 255) / 256, 256>>>(Wq, Wk, Wv, bq, bk, bv);
    prep_wo<<<(DD * DKK + 255) / 256, 256>>>(Wo);
    transpose_split_f32<<<dim3(DFFN / 32, DD / 32), tb>>>(W1, w1Th, w1Tl, DD, DFFN);
    transpose_split_f32<<<dim3(DD / 32, DFFN / 32), tb>>>(W2, w2Th, w2Tl, DFFN, DD);

    embed_kernel<<<NTOT / 512, 256>>>(ids, emb);

    for (int it = 0; it < NREP; it++) {
        // QKV fused: x @ wqkvT^T + bqkv -> qkv hi/lo [16384,192]
        mma_gemm<64, 32, 32, 3, 1, false><<<dim3(3, 128, 1), 256, SM64>>>(
            xh, xl, DD, wqkvTh, wqkvTl, DD, bqkv, 0, 0,
            0, qkvh, qkvl, 192, DD, 1.f, 0, 0);

        // attention fused: head = softmax(q k^T / 32) v
        flash_attn<<<dim3(SS / 128, BB), 256, SMFA>>>(qkvh, qkvl, headh, headl, inv_div);

        // y = head @ Wo_eff + bo + x, LN partials
        mma_gemm<128, 64, 32, 2, 0, false><<<dim3(4, 128, 1), 256, SM128>>>(
            headh, headl, DKK, woTh, woTl, DKK, bo, xh, xl,
            y, 0, 0, DD, DKK, 1.f, psum, psq);

        finalize_kernel<<<1, 256>>>(512);
        normalize_kernel<<<NTOT / 512, 256>>>(y, 0, x1h, x1l);

        // h = relu(x1 @ W1 + b1) -> hi/lo
        mma_gemm<128, 64, 32, 2, 1, true><<<dim3(16, 128, 1), 256, SM128>>>(
            x1h, x1l, DD, w1Th, w1Tl, DD, b1, 0, 0,
            0, hh, hl, DFFN, DD, 1.f, 0, 0);

        // y = h @ W2 + b2 + x1, LN partials
        mma_gemm<128, 64, 32, 2, 0, false><<<dim3(4, 128, 1), 256, SM128>>>(
            hh, hl, DFFN, w2Th, w2Tl, DFFN, b2, x1h, x1l,
            y, 0, 0, DD, DFFN, 1.f, psum, psq);

        finalize_kernel<<<1, 256>>>(512);
        if (it == NREP - 1)
            normalize_kernel<<<NTOT / 512, 256>>>(y, (float*)d_out, 0, 0);
        else
            normalize_kernel<<<NTOT / 512, 256>>>(y, 0, xh, xl);
    }
}

// round 9
// speedup vs baseline: 2.2825x; 1.2240x over previous
#include <cuda_runtime.h>
#include <cuda_bf16.h>
#include <cuda_fp16.h>
#include <math.h>
#include <stdint.h>

#define BB   8
#define SS   2048
#define DD   512
#define DKK  64
#define DFFN 2048
#define NREP 6
#define MSROWS (BB*SS)          // 16384
#define NTOT (BB*SS*DD)         // 8388608

typedef __nv_bfloat16 bf16;
typedef __half f16;

// ---------------------------------------------------------------------------
// Scratch
// ---------------------------------------------------------------------------
__device__ float g_y [NTOT];

__device__ bf16 g_xh [NTOT];
__device__ bf16 g_xl [NTOT];
__device__ f16  g_x1fh[NTOT];
__device__ f16  g_x1fl[NTOT];
__device__ bf16 g_qkvh[MSROWS*192];
__device__ bf16 g_qkvl[MSROWS*192];
__device__ bf16 g_headh[MSROWS*DKK];
__device__ bf16 g_headl[MSROWS*DKK];
__device__ f16  g_hf[(long)MSROWS*DFFN];

__device__ bf16 g_wqkvTh[192*DD];
__device__ bf16 g_wqkvTl[192*DD];
__device__ bf16 g_woTh[DD*DKK];
__device__ bf16 g_woTl[DD*DKK];
__device__ f16  g_w1fh[DFFN*DD];
__device__ f16  g_w1fl[DFFN*DD];
__device__ f16  g_w2fh[DD*DFFN];
__device__ f16  g_w2fl[DD*DFFN];
__device__ float g_bqkv[192];

__device__ float g_psum[1024];
__device__ float g_psq [1024];
__device__ float g_stats[2];

// ---------------------------------------------------------------------------
// Helpers
// ---------------------------------------------------------------------------
__device__ __forceinline__ uint32_t cvta_shared_u32(const void* p) {
    uint32_t a;
    asm("{ .reg .u64 t; cvta.to.shared.u64 t, %1; cvt.u32.u64 %0, t; }" : "=r"(a) : "l"(p));
    return a;
}
__device__ __forceinline__ void cp_async16(uint32_t saddr, const void* gptr) {
    asm volatile("cp.async.cg.shared.global [%0], [%1], 16;" :: "r"(saddr), "l"(gptr));
}
__device__ __forceinline__ void cp_commit() {
    asm volatile("cp.async.commit_group;" ::: "memory");
}
template<int N>
__device__ __forceinline__ void cp_wait() {
    asm volatile("cp.async.wait_group %0;" :: "n"(N) : "memory");
}
__device__ __forceinline__ void ldsm_x4(uint32_t& r0, uint32_t& r1, uint32_t& r2, uint32_t& r3,
                                        uint32_t addr) {
    asm volatile("ldmatrix.sync.aligned.m8n8.x4.shared.b16 {%0,%1,%2,%3}, [%4];"
                 : "=r"(r0), "=r"(r1), "=r"(r2), "=r"(r3) : "r"(addr));
}
__device__ __forceinline__ void ldsm_x4_t(uint32_t& r0, uint32_t& r1, uint32_t& r2, uint32_t& r3,
                                          uint32_t addr) {
    asm volatile("ldmatrix.sync.aligned.m8n8.x4.trans.shared.b16 {%0,%1,%2,%3}, [%4];"
                 : "=r"(r0), "=r"(r1), "=r"(r2), "=r"(r3) : "r"(addr));
}
__device__ __forceinline__ void split_bf16(float e0, float e1, uint32_t& hi, uint32_t& lo) {
    asm("cvt.rn.bf16x2.f32 %0, %1, %2;" : "=r"(hi) : "f"(e1), "f"(e0));
    float h0 = __uint_as_float(hi << 16);
    float h1 = __uint_as_float(hi & 0xffff0000u);
    float l0 = e0 - h0;
    float l1 = e1 - h1;
    asm("cvt.rn.bf16x2.f32 %0, %1, %2;" : "=r"(lo) : "f"(l1), "f"(l0));
}
__device__ __forceinline__ uint32_t pack_f16(float e0, float e1) {
    uint32_t r;
    asm("cvt.rn.f16x2.f32 %0, %1, %2;" : "=r"(r) : "f"(e1), "f"(e0));
    return r;
}
__device__ __forceinline__ void split1(float v, bf16& h, bf16& l) {
    h = __float2bfloat16_rn(v);
    l = __float2bfloat16_rn(v - __bfloat162float(h));
}
__device__ __forceinline__ void mma_bf16(float* c, const uint32_t* a, const uint32_t* b) {
    asm volatile(
        "mma.sync.aligned.m16n8k16.row.col.f32.bf16.bf16.f32 "
        "{%0,%1,%2,%3}, {%4,%5,%6,%7}, {%8,%9}, {%0,%1,%2,%3};"
        : "+f"(c[0]), "+f"(c[1]), "+f"(c[2]), "+f"(c[3])
        : "r"(a[0]), "r"(a[1]), "r"(a[2]), "r"(a[3]), "r"(b[0]), "r"(b[1]));
}
__device__ __forceinline__ void mma_f16(float* c, const uint32_t* a, const uint32_t* b) {
    asm volatile(
        "mma.sync.aligned.m16n8k16.row.col.f32.f16.f16.f32 "
        "{%0,%1,%2,%3}, {%4,%5,%6,%7}, {%8,%9}, {%0,%1,%2,%3};"
        : "+f"(c[0]), "+f"(c[1]), "+f"(c[2]), "+f"(c[3])
        : "r"(a[0]), "r"(a[1]), "r"(a[2]), "r"(a[3]), "r"(b[0]), "r"(b[1]));
}

#define SMSB 40

// ---------------------------------------------------------------------------
// bf16 3-term pre-split GEMM (QKV + Wo path). Modes:
// 0: C fp32 = acc*alpha + bias + (srch+srcl bf16), + LN partials
// 1: Chi/Clo = split(acc*alpha + bias)
// ---------------------------------------------------------------------------
template<int BN, int WM, int WN, int STAGES, int MODE>
__global__ void __launch_bounds__(256, 2)
mma_gemm(const bf16* __restrict__ Ahi, const bf16* __restrict__ Alo, int lda,
         const bf16* __restrict__ Bhi, const bf16* __restrict__ Blo, int ldb,
         const float* __restrict__ bias,
         const bf16* __restrict__ srch, const bf16* __restrict__ srcl,
         float* __restrict__ C, bf16* __restrict__ Chi, bf16* __restrict__ Clo,
         int ldc, int K, float alpha,
         float* __restrict__ psum, float* __restrict__ psq)
{
    constexpr int MT = WM / 16;
    constexpr int NT = WN / 8;
    constexpr int WARPS_N = BN / WN;
    static_assert((128 / WM) * (BN / WN) == 8, "8 warps");
    static_assert(NT % 2 == 0, "NT even");

    constexpr int OFF_ALO = 128 * SMSB;
    constexpr int OFF_BHI = 256 * SMSB;
    constexpr int OFF_BLO = OFF_BHI + BN * SMSB;
    constexpr int BUFSZ   = OFF_BLO + BN * SMSB;

    extern __shared__ bf16 smem[];
    __shared__ float s_red0[256];
    __shared__ float s_red1[256];

    const int tid  = threadIdx.x;
    const int lane = tid & 31;
    const int wid  = tid >> 5;
    const int warp_m = wid / WARPS_N;
    const int warp_n = wid % WARPS_N;
    const int qr = lane >> 2;
    const int qc = lane & 3;

    const int m0 = blockIdx.y * 128;
    const int n0 = blockIdx.x * BN;

    float acc[MT][NT][4];
#pragma unroll
    for (int i = 0; i < MT; i++)
#pragma unroll
        for (int j = 0; j < NT; j++)
#pragma unroll
            for (int u = 0; u < 4; u++) acc[i][j][u] = 0.f;

    const uint32_t sb = cvta_shared_u32(smem);

    auto load_chunk = [&](int c, int stg) {
        const int k0 = c << 5;
        const uint32_t base = sb + (uint32_t)stg * (BUFSZ * 2);
#pragma unroll
        for (int i = 0; i < 2; i++) {
            int idx = tid + i * 256;
            int row = idx >> 2, c8 = idx & 3;
            long g = (long)(m0 + row) * lda + k0 + c8 * 8;
            uint32_t so = (uint32_t)(row * SMSB + c8 * 8) * 2;
            cp_async16(base + so, Ahi + g);
            cp_async16(base + OFF_ALO * 2 + so, Alo + g);
        }
#pragma unroll
        for (int i = 0; i < BN / 64; i++) {
            int idx = tid + i * 256;
            int row = idx >> 2, c8 = idx & 3;
            long g = (long)(n0 + row) * ldb + k0 + c8 * 8;
            uint32_t so = (uint32_t)(row * SMSB + c8 * 8) * 2;
            cp_async16(base + OFF_BHI * 2 + so, Bhi + g);
            cp_async16(base + OFF_BLO * 2 + so, Blo + g);
        }
    };

    const int nch = K >> 5;
#pragma unroll
    for (int s = 0; s < STAGES - 1; s++) { load_chunk(s, s); cp_commit(); }

    const uint32_t a_off = (uint32_t)(((lane & 15) + warp_m * WM) * SMSB + (lane >> 4) * 8) * 2;
    const uint32_t b_off = (uint32_t)((((lane >> 4) & 1) * 8 + (lane & 7) + warp_n * WN) * SMSB
                                      + ((lane >> 3) & 1) * 8) * 2;

    for (int c = 0; c < nch; c++) {
        const int stg = c % STAGES;
        if (c + STAGES - 1 < nch) {
            load_chunk(c + STAGES - 1, (c + STAGES - 1) % STAGES);
            cp_commit();
            cp_wait<STAGES - 1>();
        } else {
            cp_wait<0>();
        }
        __syncthreads();

        const uint32_t stA  = sb + (uint32_t)stg * (BUFSZ * 2);
        const uint32_t stAl = stA + OFF_ALO * 2;
        const uint32_t stBh = stA + OFF_BHI * 2;
        const uint32_t stBl = stA + OFF_BLO * 2;

#pragma unroll
        for (int ks = 0; ks < 2; ks++) {
            const uint32_t kk2 = (uint32_t)ks * 32;
            uint32_t bh[NT][2], bl[NT][2];
#pragma unroll
            for (int in2 = 0; in2 < NT / 2; in2++) {
                uint32_t off = b_off + (uint32_t)in2 * (16 * SMSB * 2) + kk2;
                ldsm_x4(bh[2*in2][0], bh[2*in2][1], bh[2*in2+1][0], bh[2*in2+1][1], stBh + off);
                ldsm_x4(bl[2*in2][0], bl[2*in2][1], bl[2*in2+1][0], bl[2*in2+1][1], stBl + off);
            }
#pragma unroll
            for (int im = 0; im < MT; im++) {
                uint32_t off = a_off + (uint32_t)im * (16 * SMSB * 2) + kk2;
                uint32_t ah[4], al[4];
                ldsm_x4(ah[0], ah[1], ah[2], ah[3], stA + off);
                ldsm_x4(al[0], al[1], al[2], al[3], stAl + off);
#pragma unroll
                for (int in_ = 0; in_ < NT; in_++) {
                    mma_bf16(acc[im][in_], ah, bh[in_]);
                    mma_bf16(acc[im][in_], al, bh[in_]);
                    mma_bf16(acc[im][in_], ah, bl[in_]);
                }
            }
        }
        __syncthreads();
    }

    float lsum = 0.f, lsq = 0.f;
#pragma unroll
    for (int im = 0; im < MT; im++) {
#pragma unroll
        for (int h2 = 0; h2 < 2; h2++) {
            const int row = m0 + warp_m * WM + im * 16 + qr + h2 * 8;
#pragma unroll
            for (int in_ = 0; in_ < NT; in_++) {
                const int col = n0 + warp_n * WN + in_ * 8 + qc * 2;
                float v0 = acc[im][in_][h2 * 2 + 0] * alpha;
                float v1 = acc[im][in_][h2 * 2 + 1] * alpha;
                if (bias) { v0 += bias[col]; v1 += bias[col + 1]; }
                if (MODE == 0) {
                    long si = (long)row * ldc + col;
                    v0 += __bfloat162float(srch[si])     + __bfloat162float(srcl[si]);
                    v1 += __bfloat162float(srch[si + 1]) + __bfloat162float(srcl[si + 1]);
                    float2 o; o.x = v0; o.y = v1;
                    *reinterpret_cast<float2*>(&C[(long)row * ldc + col]) = o;
                    lsum += v0 + v1;
                    lsq  += v0 * v0 + v1 * v1;
                } else {
                    uint32_t hp, lp;
                    split_bf16(v0, v1, hp, lp);
                    *reinterpret_cast<uint32_t*>(&Chi[(long)row * ldc + col]) = hp;
                    *reinterpret_cast<uint32_t*>(&Clo[(long)row * ldc + col]) = lp;
                }
            }
        }
    }

    if (MODE == 0) {
        s_red0[tid] = lsum; s_red1[tid] = lsq;
        __syncthreads();
        for (int s = 128; s > 0; s >>= 1) {
            if (tid < s) { s_red0[tid] += s_red0[tid + s]; s_red1[tid] += s_red1[tid + s]; }
            __syncthreads();
        }
        if (tid == 0) {
            int cta = blockIdx.y * gridDim.x + blockIdx.x;
            psum[cta] = s_red0[0];
            psq [cta] = s_red1[0];
        }
    }
}

// ---------------------------------------------------------------------------
// fp16 2-term GEMM (FFN path): C = alpha * Af[M,K] @ (Bh+Bl)[N,K]^T (+bias)
//   Weights pre-scaled x1024; alpha = 1/1024. A single fp16 limb.
//   BM=128, BN=128, WM=64, WN=32, 3-stage cp.async.
// MODE 1: Cf = f16(relu(...)); MODE 0: C fp32 + residual (fp16 pair) + LN partials
// ---------------------------------------------------------------------------
template<int MODE>
__global__ void __launch_bounds__(256, 2)
ffn_gemm(const f16* __restrict__ Af, int lda,
         const f16* __restrict__ Bh, const f16* __restrict__ Bl, int ldb,
         const float* __restrict__ bias,
         const f16* __restrict__ srch, const f16* __restrict__ srcl,
         float* __restrict__ C, f16* __restrict__ Cf,
         int ldc, int K, float alpha,
         float* __restrict__ psum, float* __restrict__ psq)
{
    constexpr int BN = 128, WM = 64, WN = 32;
    constexpr int MT = 4, NT = 4;
    constexpr int STAGES = 3;
    constexpr int OFF_BH = 128 * SMSB;
    constexpr int OFF_BL = OFF_BH + BN * SMSB;
    constexpr int BUFSZ  = OFF_BL + BN * SMSB;   // f16 elems per stage

    extern __shared__ f16 smemf[];
    __shared__ float s_red0[256];
    __shared__ float s_red1[256];

    const int tid  = threadIdx.x;
    const int lane = tid & 31;
    const int wid  = tid >> 5;
    const int warp_m = wid >> 2;       // 0..1
    const int warp_n = wid & 3;        // 0..3
    const int qr = lane >> 2;
    const int qc = lane & 3;

    const int m0 = blockIdx.y * 128;
    const int n0 = blockIdx.x * BN;

    float acc[MT][NT][4];
#pragma unroll
    for (int i = 0; i < MT; i++)
#pragma unroll
        for (int j = 0; j < NT; j++)
#pragma unroll
            for (int u = 0; u < 4; u++) acc[i][j][u] = 0.f;

    const uint32_t sb = cvta_shared_u32(smemf);

    auto load_chunk = [&](int c, int stg) {
        const int k0 = c << 5;
        const uint32_t base = sb + (uint32_t)stg * (BUFSZ * 2);
#pragma unroll
        for (int i = 0; i < 2; i++) {
            int idx = tid + i * 256;
            int row = idx >> 2, c8 = idx & 3;
            long g = (long)(m0 + row) * lda + k0 + c8 * 8;
            uint32_t so = (uint32_t)(row * SMSB + c8 * 8) * 2;
            cp_async16(base + so, Af + g);
        }
#pragma unroll
        for (int i = 0; i < 2; i++) {
            int idx = tid + i * 256;
            int row = idx >> 2, c8 = idx & 3;
            long g = (long)(n0 + row) * ldb + k0 + c8 * 8;
            uint32_t so = (uint32_t)(row * SMSB + c8 * 8) * 2;
            cp_async16(base + OFF_BH * 2 + so, Bh + g);
            cp_async16(base + OFF_BL * 2 + so, Bl + g);
        }
    };

    const int nch = K >> 5;
#pragma unroll
    for (int s = 0; s < STAGES - 1; s++) { load_chunk(s, s); cp_commit(); }

    const uint32_t a_off = (uint32_t)(((lane & 15) + warp_m * WM) * SMSB + (lane >> 4) * 8) * 2;
    const uint32_t b_off = (uint32_t)((((lane >> 4) & 1) * 8 + (lane & 7) + warp_n * WN) * SMSB
                                      + ((lane >> 3) & 1) * 8) * 2;

    for (int c = 0; c < nch; c++) {
        const int stg = c % STAGES;
        if (c + STAGES - 1 < nch) {
            load_chunk(c + STAGES - 1, (c + STAGES - 1) % STAGES);
            cp_commit();
            cp_wait<STAGES - 1>();
        } else {
            cp_wait<0>();
        }
        __syncthreads();

        const uint32_t stA  = sb + (uint32_t)stg * (BUFSZ * 2);
        const uint32_t stBh = stA + OFF_BH * 2;
        const uint32_t stBl = stA + OFF_BL * 2;

#pragma unroll
        for (int ks = 0; ks < 2; ks++) {
            const uint32_t kk2 = (uint32_t)ks * 32;
            uint32_t bh[NT][2], bl[NT][2];
#pragma unroll
            for (int in2 = 0; in2 < NT / 2; in2++) {
                uint32_t off = b_off + (uint32_t)in2 * (16 * SMSB * 2) + kk2;
                ldsm_x4(bh[2*in2][0], bh[2*in2][1], bh[2*in2+1][0], bh[2*in2+1][1], stBh + off);
                ldsm_x4(bl[2*in2][0], bl[2*in2][1], bl[2*in2+1][0], bl[2*in2+1][1], stBl + off);
            }
#pragma unroll
            for (int im = 0; im < MT; im++) {
                uint32_t off = a_off + (uint32_t)im * (16 * SMSB * 2) + kk2;
                uint32_t ah[4];
                ldsm_x4(ah[0], ah[1], ah[2], ah[3], stA + off);
#pragma unroll
                for (int in_ = 0; in_ < NT; in_++) {
                    mma_f16(acc[im][in_], ah, bh[in_]);
                    mma_f16(acc[im][in_], ah, bl[in_]);
                }
            }
        }
        __syncthreads();
    }

    float lsum = 0.f, lsq = 0.f;
#pragma unroll
    for (int im = 0; im < MT; im++) {
#pragma unroll
        for (int h2 = 0; h2 < 2; h2++) {
            const int row = m0 + warp_m * WM + im * 16 + qr + h2 * 8;
#pragma unroll
            for (int in_ = 0; in_ < NT; in_++) {
                const int col = n0 + warp_n * WN + in_ * 8 + qc * 2;
                float v0 = acc[im][in_][h2 * 2 + 0] * alpha + bias[col];
                float v1 = acc[im][in_][h2 * 2 + 1] * alpha + bias[col + 1];
                if (MODE == 0) {
                    long si = (long)row * ldc + col;
                    v0 += __half2float(srch[si])     + __half2float(srcl[si]);
                    v1 += __half2float(srch[si + 1]) + __half2float(srcl[si + 1]);
                    float2 o; o.x = v0; o.y = v1;
                    *reinterpret_cast<float2*>(&C[(long)row * ldc + col]) = o;
                    lsum += v0 + v1;
                    lsq  += v0 * v0 + v1 * v1;
                } else {
                    v0 = fmaxf(v0, 0.f); v1 = fmaxf(v1, 0.f);
                    *reinterpret_cast<uint32_t*>(&Cf[(long)row * ldc + col]) = pack_f16(v0, v1);
                }
            }
        }
    }

    if (MODE == 0) {
        s_red0[tid] = lsum; s_red1[tid] = lsq;
        __syncthreads();
        for (int s = 128; s > 0; s >>= 1) {
            if (tid < s) { s_red0[tid] += s_red0[tid + s]; s_red1[tid] += s_red1[tid + s]; }
            __syncthreads();
        }
        if (tid == 0) {
            int cta = blockIdx.y * gridDim.x + blockIdx.x;
            psum[cta] = s_red0[0];
            psq [cta] = s_red1[0];
        }
    }
}

// ---------------------------------------------------------------------------
// Flash attention (3-term bf16, unchanged from round 8)
// ---------------------------------------------------------------------------
#define FAS 72

__global__ void __launch_bounds__(256)
flash_attn(const bf16* __restrict__ qkvh, const bf16* __restrict__ qkvl,
           bf16* __restrict__ headh, bf16* __restrict__ headl, float alpha)
{
    constexpr int QSZ = 128 * FAS;
    constexpr int CSZ = 64 * FAS;

    extern __shared__ bf16 fsm[];
    const uint32_t sb = cvta_shared_u32(fsm);
    const uint32_t qh_a = sb;
    const uint32_t ql_a = sb + QSZ * 2;
    const uint32_t ck_a = sb + 2 * QSZ * 2;

    const int tid  = threadIdx.x;
    const int lane = tid & 31;
    const int wid  = tid >> 5;
    const int qr = lane >> 2, qc = lane & 3;
    const long bz = blockIdx.y;
    const long grow0 = bz * SS + blockIdx.x * 128;

#pragma unroll
    for (int i = 0; i < 4; i++) {
        int idx = tid + i * 256;
        int r = idx >> 3, s = idx & 7;
        long g = (grow0 + r) * 192 + s * 8;
        uint32_t so = (uint32_t)(r * FAS + s * 8) * 2;
        cp_async16(qh_a + so, qkvh + g);
        cp_async16(ql_a + so, qkvl + g);
    }
    cp_commit();

    auto load_chunk = [&](int c, int buf) {
        const uint32_t base = ck_a + (uint32_t)buf * 4 * CSZ * 2;
#pragma unroll
        for (int i = 0; i < 2; i++) {
            int idx = tid + i * 256;
            int r = idx >> 3, s = idx & 7;
            long g = (bz * SS + c * 64 + r) * 192 + s * 8;
            uint32_t so = (uint32_t)(r * FAS + s * 8) * 2;
            cp_async16(base + so,               qkvh + g + 64);
            cp_async16(base + CSZ * 2 + so,     qkvl + g + 64);
            cp_async16(base + 2 * CSZ * 2 + so, qkvh + g + 128);
            cp_async16(base + 3 * CSZ * 2 + so, qkvl + g + 128);
        }
        cp_commit();
    };

    load_chunk(0, 0);
    cp_wait<1>();
    __syncthreads();

    const uint32_t qa_off = (uint32_t)((lane & 15) + wid * 16) * (FAS * 2) + (lane >> 4) * 16;
    uint32_t qah[4][4], qal[4][4];
#pragma unroll
    for (int ks = 0; ks < 4; ks++) {
        ldsm_x4(qah[ks][0], qah[ks][1], qah[ks][2], qah[ks][3], qh_a + qa_off + ks * 32);
        ldsm_x4(qal[ks][0], qal[ks][1], qal[ks][2], qal[ks][3], ql_a + qa_off + ks * 32);
    }

    const uint32_t kb_off = (uint32_t)((((lane >> 4) & 1) * 8 + (lane & 7)) * FAS) * 2
                            + ((lane >> 3) & 1) * 16;
    const uint32_t vb_off = (uint32_t)(((lane & 7) + ((lane >> 3) & 1) * 8) * FAS) * 2
                            + ((lane >> 4) & 1) * 16;

    float o[8][4];
#pragma unroll
    for (int t = 0; t < 8; t++)
#pragma unroll
        for (int u = 0; u < 4; u++) o[t][u] = 0.f;
    float rs0 = 0.f, rs1 = 0.f;

    for (int c = 0; c < SS / 64; c++) {
        const int buf = c & 1;
        cp_wait<0>();
        __syncthreads();
        if (c + 1 < SS / 64) load_chunk(c + 1, buf ^ 1);

        const uint32_t kh_a = ck_a + (uint32_t)buf * 4 * CSZ * 2;
        const uint32_t kl_a = kh_a + CSZ * 2;
        const uint32_t vh_a = kh_a + 2 * CSZ * 2;
        const uint32_t vl_a = kh_a + 3 * CSZ * 2;

        float s[8][4];
#pragma unroll
        for (int j = 0; j < 8; j++)
#pragma unroll
            for (int u = 0; u < 4; u++) s[j][u] = 0.f;

#pragma unroll
        for (int ks = 0; ks < 4; ks++) {
            uint32_t kbh[8][2], kbl[8][2];
#pragma unroll
            for (int j4 = 0; j4 < 4; j4++) {
                uint32_t off = kb_off + (uint32_t)j4 * (16 * FAS * 2) + ks * 32;
                ldsm_x4(kbh[2*j4][0], kbh[2*j4][1], kbh[2*j4+1][0], kbh[2*j4+1][1], kh_a + off);
                ldsm_x4(kbl[2*j4][0], kbl[2*j4][1], kbl[2*j4+1][0], kbl[2*j4+1][1], kl_a + off);
            }
#pragma unroll
            for (int j = 0; j < 8; j++) {
                mma_bf16(s[j], qah[ks], kbh[j]);
                mma_bf16(s[j], qal[ks], kbh[j]);
                mma_bf16(s[j], qah[ks], kbl[j]);
            }
        }

        uint32_t pah[4][4], pal[4][4];
#pragma unroll
        for (int j = 0; j < 8; j++) {
            float p0 = __expf(s[j][0] * alpha);
            float p1 = __expf(s[j][1] * alpha);
            float p2 = __expf(s[j][2] * alpha);
            float p3 = __expf(s[j][3] * alpha);
            rs0 += p0 + p1;
            rs1 += p2 + p3;
            int ks = j >> 1, half = (j & 1) * 2;
            split_bf16(p0, p1, pah[ks][half + 0], pal[ks][half + 0]);
            split_bf16(p2, p3, pah[ks][half + 1], pal[ks][half + 1]);
        }

#pragma unroll
        for (int ks = 0; ks < 4; ks++) {
            uint32_t vbh[8][2], vbl[8][2];
#pragma unroll
            for (int i = 0; i < 4; i++) {
                uint32_t off = vb_off + (uint32_t)ks * (16 * FAS * 2) + i * 32;
                ldsm_x4_t(vbh[2*i][0], vbh[2*i][1], vbh[2*i+1][0], vbh[2*i+1][1], vh_a + off);
                ldsm_x4_t(vbl[2*i][0], vbl[2*i][1], vbl[2*i+1][0], vbl[2*i+1][1], vl_a + off);
            }
#pragma unroll
            for (int t = 0; t < 8; t++) {
                mma_bf16(o[t], pah[ks], vbh[t]);
                mma_bf16(o[t], pal[ks], vbh[t]);
                mma_bf16(o[t], pah[ks], vbl[t]);
            }
        }
    }

    rs0 += __shfl_xor_sync(0xffffffffu, rs0, 1);
    rs0 += __shfl_xor_sync(0xffffffffu, rs0, 2);
    rs1 += __shfl_xor_sync(0xffffffffu, rs1, 1);
    rs1 += __shfl_xor_sync(0xffffffffu, rs1, 2);
    float inv0 = 1.0f / rs0;
    float inv1 = 1.0f / rs1;

    long g0 = grow0 + wid * 16 + qr;
#pragma unroll
    for (int t = 0; t < 8; t++) {
        int col = t * 8 + qc * 2;
        uint32_t hp, lp;
        split_bf16(o[t][0] * inv0, o[t][1] * inv0, hp, lp);
        *reinterpret_cast<uint32_t*>(&headh[g0 * DKK + col]) = hp;
        *reinterpret_cast<uint32_t*>(&headl[g0 * DKK + col]) = lp;
        split_bf16(o[t][2] * inv1, o[t][3] * inv1, hp, lp);
        *reinterpret_cast<uint32_t*>(&headh[(g0 + 8) * DKK + col]) = hp;
        *reinterpret_cast<uint32_t*>(&headl[(g0 + 8) * DKK + col]) = lp;
    }
}

// ---------------------------------------------------------------------------
// Weight prep
// ---------------------------------------------------------------------------
__global__ void transpose_split_f16(const float* __restrict__ in,
                                    f16* __restrict__ oh, f16* __restrict__ ol,
                                    int R, int C_) {
    __shared__ float tt[32][33];
    int r0 = blockIdx.y * 32, c0 = blockIdx.x * 32;
#pragma unroll
    for (int i = 0; i < 32; i += 8)
        tt[threadIdx.y + i][threadIdx.x] = in[(long)(r0 + threadIdx.y + i) * C_ + c0 + threadIdx.x];
    __syncthreads();
#pragma unroll
    for (int i = 0; i < 32; i += 8) {
        long o = (long)(c0 + threadIdx.y + i) * R + r0 + threadIdx.x;
        float w = tt[threadIdx.x][threadIdx.y + i];
        f16 wh = __float2half_rn(w);
        float whf = __half2float(wh);
        oh[o] = __float2half_rn(whf * 1024.0f);          // exact (pow2 scale)
        ol[o] = __float2half_rn((w - whf) * 1024.0f);
    }
}

__global__ void prep_qkvw(const float* __restrict__ Wq, const float* __restrict__ Wk,
                          const float* __restrict__ Wv, const float* __restrict__ bq,
                          const float* __restrict__ bk, const float* __restrict__ bv) {
    int idx = blockIdx.x * 256 + threadIdx.x;
    if (idx < 192 * DD) {
        int n = idx >> 9, k = idx & 511;
        const float* W = (n < 64) ? Wq : ((n < 128) ? Wk : Wv);
        float v = W[k * DKK + (n & 63)];
        split1(v, g_wqkvTh[idx], g_wqkvTl[idx]);
    }
    if (idx < 192) {
        g_bqkv[idx] = (idx < 64) ? bq[idx] : ((idx < 128) ? bk[idx - 64] : bv[idx - 128]);
    }
}

__global__ void prep_wo(const float* __restrict__ Wo) {
    int idx = blockIdx.x * 256 + threadIdx.x;
    if (idx >= DD * DKK) return;
    int e = idx / DKK, t = idx % DKK;
    float s = 0.f;
#pragma unroll
    for (int j = 0; j < 8; j++) s += Wo[(j * DKK + t) * DD + e];
    split1(s, g_woTh[idx], g_woTl[idx]);
}

// ---------------------------------------------------------------------------
// Embedding + positional encoding
// ---------------------------------------------------------------------------
__global__ void embed_kernel(const int* __restrict__ ids, const float* __restrict__ emb) {
    long i2 = (long)blockIdx.x * 256 + threadIdx.x;
    if (i2 >= NTOT / 2) return;
    long e = i2 * 2;
    int d  = (int)(e & (DD - 1));
    int bs = (int)(e >> 9);
    int s  = bs & (SS - 1);
    int id = ids[bs];
    float v0 = 0.f, v1 = 0.f;
    if (id != 0) {
        const float* er = emb + (long)id * DD;
        v0 = er[d]; v1 = er[d + 1];
    }
    double f0 = pow(10000.0, (double)d / 256.0);
    double f1 = pow(10000.0, (double)(d + 1) / 256.0);
    v0 += sinf((float)((double)s / f0));
    v1 += cosf((float)((double)s / f1));
    uint32_t hp, lp;
    split_bf16(v0, v1, hp, lp);
    *reinterpret_cast<uint32_t*>(&g_xh[e]) = hp;
    *reinterpret_cast<uint32_t*>(&g_xl[e]) = lp;
}

// ---------------------------------------------------------------------------
// LayerNorm finalize + normalize variants
// ---------------------------------------------------------------------------
__global__ void finalize_kernel(int n) {
    __shared__ double ds[256], dq[256];
    double a = 0.0, b = 0.0;
    for (int i = threadIdx.x; i < n; i += 256) {
        a += (double)g_psum[i];
        b += (double)g_psq[i];
    }
    ds[threadIdx.x] = a; dq[threadIdx.x] = b; __syncthreads();
    for (int s = 128; s > 0; s >>= 1) {
        if (threadIdx.x < s) {
            ds[threadIdx.x] += ds[threadIdx.x + s];
            dq[threadIdx.x] += dq[threadIdx.x + s];
        }
        __syncthreads();
    }
    if (threadIdx.x == 0) {
        double m = ds[0] / (double)NTOT;
        double v = dq[0] / (double)NTOT - m * m;
        g_stats[0] = (float)m;
        g_stats[1] = (float)(1.0 / sqrt(v + 1e-5));
    }
}

// writes bf16 hi/lo pair (x path) or fp32 (final)
__global__ void normalize_bf16(const float* __restrict__ y, float* __restrict__ out,
                               bf16* __restrict__ oh, bf16* __restrict__ ol) {
    long i2 = (long)blockIdx.x * 256 + threadIdx.x;
    long e = i2 * 2;
    if (e >= NTOT) return;
    float m = g_stats[0], rs = g_stats[1];
    float2 yy = *reinterpret_cast<const float2*>(&y[e]);
    float v0 = (yy.x - m) * rs, v1 = (yy.y - m) * rs;
    if (out) {
        float2 o; o.x = v0; o.y = v1;
        *reinterpret_cast<float2*>(&out[e]) = o;
    }
    if (oh) {
        uint32_t hp, lp;
        split_bf16(v0, v1, hp, lp);
        *reinterpret_cast<uint32_t*>(&oh[e]) = hp;
        *reinterpret_cast<uint32_t*>(&ol[e]) = lp;
    }
}

// writes fp16 hi/lo pair (x1 path)
__global__ void normalize_f16(const float* __restrict__ y,
                              f16* __restrict__ oh, f16* __restrict__ ol) {
    long i2 = (long)blockIdx.x * 256 + threadIdx.x;
    long e = i2 * 2;
    if (e >= NTOT) return;
    float m = g_stats[0], rs = g_stats[1];
    float2 yy = *reinterpret_cast<const float2*>(&y[e]);
    float v0 = (yy.x - m) * rs, v1 = (yy.y - m) * rs;
    f16 h0 = __float2half_rn(v0);
    f16 h1 = __float2half_rn(v1);
    float l0 = v0 - __half2float(h0);
    float l1 = v1 - __half2float(h1);
    *reinterpret_cast<uint32_t*>(&oh[e]) =
        ((uint32_t)__half_as_ushort(h1) << 16) | __half_as_ushort(h0);
    *reinterpret_cast<uint32_t*>(&ol[e]) = pack_f16(l0, l1);
}

// ---------------------------------------------------------------------------
// Launch
// ---------------------------------------------------------------------------
extern "C" void kernel_launch(void* const* d_in, const int* in_sizes, int n_in,
                              void* d_out, int out_size)
{
    const int*   ids = (const int*)  d_in[0];
    const float* emb = (const float*)d_in[1];
    const float* Wq  = (const float*)d_in[2];
    const float* bq  = (const float*)d_in[3];
    const float* Wk  = (const float*)d_in[4];
    const float* bk  = (const float*)d_in[5];
    const float* Wv  = (const float*)d_in[6];
    const float* bv  = (const float*)d_in[7];
    const float* Wo  = (const float*)d_in[8];
    const float* bo  = (const float*)d_in[9];
    const float* W1  = (const float*)d_in[10];
    const float* b1  = (const float*)d_in[11];
    const float* W2  = (const float*)d_in[12];
    const float* b2  = (const float*)d_in[13];

    float *y, *bqkv, *psum, *psq;
    bf16 *xh, *xl, *qkvh, *qkvl, *headh, *headl;
    bf16 *wqkvTh, *wqkvTl, *woTh, *woTl;
    f16 *x1fh, *x1fl, *hf, *w1fh, *w1fl, *w2fh, *w2fl;
    cudaGetSymbolAddress((void**)&y,      g_y);
    cudaGetSymbolAddress((void**)&xh,     g_xh);
    cudaGetSymbolAddress((void**)&xl,     g_xl);
    cudaGetSymbolAddress((void**)&x1fh,   g_x1fh);
    cudaGetSymbolAddress((void**)&x1fl,   g_x1fl);
    cudaGetSymbolAddress((void**)&qkvh,   g_qkvh);
    cudaGetSymbolAddress((void**)&qkvl,   g_qkvl);
    cudaGetSymbolAddress((void**)&headh,  g_headh);
    cudaGetSymbolAddress((void**)&headl,  g_headl);
    cudaGetSymbolAddress((void**)&hf,     g_hf);
    cudaGetSymbolAddress((void**)&wqkvTh, g_wqkvTh);
    cudaGetSymbolAddress((void**)&wqkvTl, g_wqkvTl);
    cudaGetSymbolAddress((void**)&woTh,   g_woTh);
    cudaGetSymbolAddress((void**)&woTl,   g_woTl);
    cudaGetSymbolAddress((void**)&w1fh,   g_w1fh);
    cudaGetSymbolAddress((void**)&w1fl,   g_w1fl);
    cudaGetSymbolAddress((void**)&w2fh,   g_w2fh);
    cudaGetSymbolAddress((void**)&w2fl,   g_w2fl);
    cudaGetSymbolAddress((void**)&bqkv,   g_bqkv);
    cudaGetSymbolAddress((void**)&psum,   g_psum);
    cudaGetSymbolAddress((void**)&psq,    g_psq);

    const int SM128 = 2 * (256 + 256) * SMSB * 2;                 // 81920
    const int SM64  = 3 * (256 + 128) * SMSB * 2;                 // 92160
    const int SMF   = 3 * (128 + 256) * SMSB * 2;                 // 92160
    const int SMFA  = (2 * 128 * FAS + 8 * 64 * FAS) * 2;         // 110592

    cudaFuncSetAttribute((const void*)mma_gemm<64, 32, 32, 3, 1>,
                         cudaFuncAttributeMaxDynamicSharedMemorySize, SM64);
    cudaFuncSetAttribute((const void*)mma_gemm<128, 64, 32, 2, 0>,
                         cudaFuncAttributeMaxDynamicSharedMemorySize, SM128);
    cudaFuncSetAttribute((const void*)ffn_gemm<0>,
                         cudaFuncAttributeMaxDynamicSharedMemorySize, SMF);
    cudaFuncSetAttribute((const void*)ffn_gemm<1>,
                         cudaFuncAttributeMaxDynamicSharedMemorySize, SMF);
    cudaFuncSetAttribute((const void*)flash_attn,
                         cudaFuncAttributeMaxDynamicSharedMemorySize, SMFA);

    const float inv_div = 1.0f / 32.0f;
    const float inv_ws  = 1.0f / 1024.0f;
    dim3 tb(32, 8);

    // ---- weight prep ----
    prep_qkvw<<<(192 * DD + 255) / 256, 256>>>(Wq, Wk, Wv, bq, bk, bv);
    prep_wo<<<(DD * DKK + 255) / 256, 256>>>(Wo);
    transpose_split_f16<<<dim3(DFFN / 32, DD / 32), tb>>>(W1, w1fh, w1fl, DD, DFFN);
    transpose_split_f16<<<dim3(DD / 32, DFFN / 32), tb>>>(W2, w2fh, w2fl, DFFN, DD);

    embed_kernel<<<NTOT / 512, 256>>>(ids, emb);

    for (int it = 0; it < NREP; it++) {
        // QKV fused (bf16 3-term): x @ wqkvT^T + bqkv -> qkv hi/lo
        mma_gemm<64, 32, 32, 3, 1><<<dim3(3, 128, 1), 256, SM64>>>(
            xh, xl, DD, wqkvTh, wqkvTl, DD, bqkv, 0, 0,
            0, qkvh, qkvl, 192, DD, 1.f, 0, 0);

        // flash attention: head = softmax(q k^T / 32) v
        flash_attn<<<dim3(SS / 128, BB), 256, SMFA>>>(qkvh, qkvl, headh, headl, inv_div);

        // y = head @ Wo_eff + bo + x, LN partials (bf16 3-term)
        mma_gemm<128, 64, 32, 2, 0><<<dim3(4, 128, 1), 256, SM128>>>(
            headh, headl, DKK, woTh, woTl, DKK, bo, xh, xl,
            y, 0, 0, DD, DKK, 1.f, psum, psq);

        finalize_kernel<<<1, 256>>>(512);
        normalize_f16<<<NTOT / 512, 256>>>(y, x1fh, x1fl);

        // h = relu(x1 @ W1 + b1) -> fp16 (2-term fp16, weights x1024)
        ffn_gemm<1><<<dim3(DFFN / 128, 128, 1), 256, SMF>>>(
            x1fh, DD, w1fh, w1fl, DD, b1, 0, 0,
            0, hf, DFFN, DD, inv_ws, 0, 0);

        // y = h @ W2 + b2 + x1, LN partials (2-term fp16)
        ffn_gemm<0><<<dim3(DD / 128, 128, 1), 256, SMF>>>(
            hf, DFFN, w2fh, w2fl, DFFN, b2, x1fh, x1fl,
            y, 0, DD, DFFN, inv_ws, psum, psq);

        finalize_kernel<<<1, 256>>>(512);
        if (it == NREP - 1)
            normalize_bf16<<<NTOT / 512, 256>>>(y, (float*)d_out, 0, 0);
        else
            normalize_bf16<<<NTOT / 512, 256>>>(y, 0, xh, xl);
    }
}

// round 10
// speedup vs baseline: 2.3709x; 1.0387x over previous
#include <cuda_runtime.h>
#include <cuda_fp16.h>
#include <math.h>
#include <stdint.h>

#define BB   8
#define SS   2048
#define DD   512
#define DKK  64
#define DFFN 2048
#define NREP 6
#define MSROWS (BB*SS)          // 16384
#define NTOT (BB*SS*DD)         // 8388608

typedef __half f16;

// ---------------------------------------------------------------------------
// Scratch (all fp16 operands; fp32 only for pre-LN stream y)
// ---------------------------------------------------------------------------
__device__ float g_y [NTOT];

__device__ f16 g_xfh [NTOT];
__device__ f16 g_xfl [NTOT];
__device__ f16 g_x1fh[NTOT];
__device__ f16 g_x1fl[NTOT];
__device__ f16 g_qkvfh[MSROWS*192];
__device__ f16 g_qkvfl[MSROWS*192];
__device__ f16 g_headf[MSROWS*DKK];
__device__ f16 g_hf[(long)MSROWS*DFFN];

__device__ f16 g_wqkvfh[192*DD];
__device__ f16 g_wqkvfl[192*DD];
__device__ f16 g_wofh[DD*DKK];
__device__ f16 g_wofl[DD*DKK];
__device__ f16 g_w1fh[DFFN*DD];
__device__ f16 g_w1fl[DFFN*DD];
__device__ f16 g_w2fh[DD*DFFN];
__device__ f16 g_w2fl[DD*DFFN];
__device__ float g_bqkv[192];

__device__ float g_psum[1024];
__device__ float g_psq [1024];
__device__ float g_stats[2];

// ---------------------------------------------------------------------------
// Helpers
// ---------------------------------------------------------------------------
__device__ __forceinline__ uint32_t cvta_shared_u32(const void* p) {
    uint32_t a;
    asm("{ .reg .u64 t; cvta.to.shared.u64 t, %1; cvt.u32.u64 %0, t; }" : "=r"(a) : "l"(p));
    return a;
}
__device__ __forceinline__ void cp_async16(uint32_t saddr, const void* gptr) {
    asm volatile("cp.async.cg.shared.global [%0], [%1], 16;" :: "r"(saddr), "l"(gptr));
}
__device__ __forceinline__ void cp_commit() {
    asm volatile("cp.async.commit_group;" ::: "memory");
}
template<int N>
__device__ __forceinline__ void cp_wait() {
    asm volatile("cp.async.wait_group %0;" :: "n"(N) : "memory");
}
__device__ __forceinline__ void ldsm_x4(uint32_t& r0, uint32_t& r1, uint32_t& r2, uint32_t& r3,
                                        uint32_t addr) {
    asm volatile("ldmatrix.sync.aligned.m8n8.x4.shared.b16 {%0,%1,%2,%3}, [%4];"
                 : "=r"(r0), "=r"(r1), "=r"(r2), "=r"(r3) : "r"(addr));
}
__device__ __forceinline__ void ldsm_x4_t(uint32_t& r0, uint32_t& r1, uint32_t& r2, uint32_t& r3,
                                          uint32_t addr) {
    asm volatile("ldmatrix.sync.aligned.m8n8.x4.trans.shared.b16 {%0,%1,%2,%3}, [%4];"
                 : "=r"(r0), "=r"(r1), "=r"(r2), "=r"(r3) : "r"(addr));
}
__device__ __forceinline__ uint32_t pack_f16(float e0, float e1) {
    uint32_t r;
    asm("cvt.rn.f16x2.f32 %0, %1, %2;" : "=r"(r) : "f"(e1), "f"(e0));
    return r;
}
// fp32 pair -> fp16 hi/lo packed pairs
__device__ __forceinline__ void split_f16p(float e0, float e1, uint32_t& hi, uint32_t& lo) {
    f16 h0 = __float2half_rn(e0);
    f16 h1 = __float2half_rn(e1);
    float l0 = e0 - __half2float(h0);
    float l1 = e1 - __half2float(h1);
    hi = ((uint32_t)__half_as_ushort(h1) << 16) | __half_as_ushort(h0);
    lo = pack_f16(l0, l1);
}
__device__ __forceinline__ void mma_f16(float* c, const uint32_t* a, const uint32_t* b) {
    asm volatile(
        "mma.sync.aligned.m16n8k16.row.col.f32.f16.f16.f32 "
        "{%0,%1,%2,%3}, {%4,%5,%6,%7}, {%8,%9}, {%0,%1,%2,%3};"
        : "+f"(c[0]), "+f"(c[1]), "+f"(c[2]), "+f"(c[3])
        : "r"(a[0]), "r"(a[1]), "r"(a[2]), "r"(a[3]), "r"(b[0]), "r"(b[1]));
}

#define SMSB 40

// ---------------------------------------------------------------------------
// Unified 2-term fp16 GEMM: C = alpha * Af[M,K] @ (Bh+Bl)[N,K]^T + bias
//   (weights pre-scaled x1024; alpha folds it back). BM=128.
// MODE 0: fp32 C + residual (f16 pair) + LN partials
// MODE 1: f16 single out, ReLU
// MODE 2: f16 hi/lo pair out
// ---------------------------------------------------------------------------
template<int BN, int WM, int WN, int MODE>
__global__ void __launch_bounds__(256, 2)
gemm2(const f16* __restrict__ Af, int lda,
      const f16* __restrict__ Bh, const f16* __restrict__ Bl, int ldb,
      const float* __restrict__ bias,
      const f16* __restrict__ srch, const f16* __restrict__ srcl,
      float* __restrict__ C, f16* __restrict__ Cf, f16* __restrict__ Cfl,
      int ldc, int K, float alpha,
      float* __restrict__ psum, float* __restrict__ psq)
{
    constexpr int MT = WM / 16;
    constexpr int NT = WN / 8;
    constexpr int WARPS_N = BN / WN;
    static_assert((128 / WM) * (BN / WN) == 8, "8 warps");
    static_assert(NT % 2 == 0, "NT even");
    constexpr int STAGES = 3;
    constexpr int OFF_BH = 128 * SMSB;
    constexpr int OFF_BL = OFF_BH + BN * SMSB;
    constexpr int BUFSZ  = OFF_BL + BN * SMSB;   // f16 elems per stage
    constexpr int BITER  = (BN * 4) / 256;       // B-limb load iters (1 or 2)

    extern __shared__ f16 smemf[];
    __shared__ float s_red0[256];
    __shared__ float s_red1[256];

    const int tid  = threadIdx.x;
    const int lane = tid & 31;
    const int wid  = tid >> 5;
    const int warp_m = wid / WARPS_N;
    const int warp_n = wid % WARPS_N;
    const int qr = lane >> 2;
    const int qc = lane & 3;

    const int m0 = blockIdx.y * 128;
    const int n0 = blockIdx.x * BN;

    float acc[MT][NT][4];
#pragma unroll
    for (int i = 0; i < MT; i++)
#pragma unroll
        for (int j = 0; j < NT; j++)
#pragma unroll
            for (int u = 0; u < 4; u++) acc[i][j][u] = 0.f;

    const uint32_t sb = cvta_shared_u32(smemf);

    auto load_chunk = [&](int c, int stg) {
        const int k0 = c << 5;
        const uint32_t base = sb + (uint32_t)stg * (BUFSZ * 2);
#pragma unroll
        for (int i = 0; i < 2; i++) {
            int idx = tid + i * 256;
            int row = idx >> 2, c8 = idx & 3;
            long g = (long)(m0 + row) * lda + k0 + c8 * 8;
            uint32_t so = (uint32_t)(row * SMSB + c8 * 8) * 2;
            cp_async16(base + so, Af + g);
        }
#pragma unroll
        for (int i = 0; i < BITER; i++) {
            int idx = tid + i * 256;
            int row = idx >> 2, c8 = idx & 3;
            long g = (long)(n0 + row) * ldb + k0 + c8 * 8;
            uint32_t so = (uint32_t)(row * SMSB + c8 * 8) * 2;
            cp_async16(base + OFF_BH * 2 + so, Bh + g);
            cp_async16(base + OFF_BL * 2 + so, Bl + g);
        }
    };

    const int nch = K >> 5;
#pragma unroll
    for (int s = 0; s < STAGES - 1; s++) { load_chunk(s, s); cp_commit(); }

    const uint32_t a_off = (uint32_t)(((lane & 15) + warp_m * WM) * SMSB + (lane >> 4) * 8) * 2;
    const uint32_t b_off = (uint32_t)((((lane >> 4) & 1) * 8 + (lane & 7) + warp_n * WN) * SMSB
                                      + ((lane >> 3) & 1) * 8) * 2;

    for (int c = 0; c < nch; c++) {
        const int stg = c % STAGES;
        if (c + STAGES - 1 < nch) {
            load_chunk(c + STAGES - 1, (c + STAGES - 1) % STAGES);
            cp_commit();
            cp_wait<STAGES - 1>();
        } else {
            cp_wait<0>();
        }
        __syncthreads();

        const uint32_t stA  = sb + (uint32_t)stg * (BUFSZ * 2);
        const uint32_t stBh = stA + OFF_BH * 2;
        const uint32_t stBl = stA + OFF_BL * 2;

#pragma unroll
        for (int ks = 0; ks < 2; ks++) {
            const uint32_t kk2 = (uint32_t)ks * 32;
            uint32_t bh[NT][2], bl[NT][2];
#pragma unroll
            for (int in2 = 0; in2 < NT / 2; in2++) {
                uint32_t off = b_off + (uint32_t)in2 * (16 * SMSB * 2) + kk2;
                ldsm_x4(bh[2*in2][0], bh[2*in2][1], bh[2*in2+1][0], bh[2*in2+1][1], stBh + off);
                ldsm_x4(bl[2*in2][0], bl[2*in2][1], bl[2*in2+1][0], bl[2*in2+1][1], stBl + off);
            }
#pragma unroll
            for (int im = 0; im < MT; im++) {
                uint32_t off = a_off + (uint32_t)im * (16 * SMSB * 2) + kk2;
                uint32_t ah[4];
                ldsm_x4(ah[0], ah[1], ah[2], ah[3], stA + off);
#pragma unroll
                for (int in_ = 0; in_ < NT; in_++) {
                    mma_f16(acc[im][in_], ah, bh[in_]);
                    mma_f16(acc[im][in_], ah, bl[in_]);
                }
            }
        }
        __syncthreads();
    }

    float lsum = 0.f, lsq = 0.f;
#pragma unroll
    for (int im = 0; im < MT; im++) {
#pragma unroll
        for (int h2 = 0; h2 < 2; h2++) {
            const int row = m0 + warp_m * WM + im * 16 + qr + h2 * 8;
#pragma unroll
            for (int in_ = 0; in_ < NT; in_++) {
                const int col = n0 + warp_n * WN + in_ * 8 + qc * 2;
                float v0 = acc[im][in_][h2 * 2 + 0] * alpha + bias[col];
                float v1 = acc[im][in_][h2 * 2 + 1] * alpha + bias[col + 1];
                if (MODE == 0) {
                    long si = (long)row * ldc + col;
                    v0 += __half2float(srch[si])     + __half2float(srcl[si]);
                    v1 += __half2float(srch[si + 1]) + __half2float(srcl[si + 1]);
                    float2 o; o.x = v0; o.y = v1;
                    *reinterpret_cast<float2*>(&C[(long)row * ldc + col]) = o;
                    lsum += v0 + v1;
                    lsq  += v0 * v0 + v1 * v1;
                } else if (MODE == 1) {
                    v0 = fmaxf(v0, 0.f); v1 = fmaxf(v1, 0.f);
                    *reinterpret_cast<uint32_t*>(&Cf[(long)row * ldc + col]) = pack_f16(v0, v1);
                } else {
                    uint32_t hp, lp;
                    split_f16p(v0, v1, hp, lp);
                    *reinterpret_cast<uint32_t*>(&Cf [(long)row * ldc + col]) = hp;
                    *reinterpret_cast<uint32_t*>(&Cfl[(long)row * ldc + col]) = lp;
                }
            }
        }
    }

    if (MODE == 0) {
        s_red0[tid] = lsum; s_red1[tid] = lsq;
        __syncthreads();
        for (int s = 128; s > 0; s >>= 1) {
            if (tid < s) { s_red0[tid] += s_red0[tid + s]; s_red1[tid] += s_red1[tid + s]; }
            __syncthreads();
        }
        if (tid == 0) {
            int cta = blockIdx.y * gridDim.x + blockIdx.x;
            psum[cta] = s_red0[0];
            psq [cta] = s_red1[0];
        }
    }
}

// ---------------------------------------------------------------------------
// Flash attention v2 (2-term fp16): 64 q-rows/CTA, 256 CTAs, 8 warps =
// 4 row-tiles x 2 key-halves; partial (O, Z) merged via smem at the end.
//   S = q(single) @ (kh+kl)^T; P = exp(alpha*S) single f16; O += P @ (vh+vl).
// ---------------------------------------------------------------------------
#define FAS 72

__global__ void __launch_bounds__(256, 2)
flash_attn(const f16* __restrict__ qkvfh, const f16* __restrict__ qkvfl,
           f16* __restrict__ headf, float alpha)
{
    constexpr int QSZ = 64 * FAS;   // elems
    constexpr int CSZ = 64 * FAS;

    extern __shared__ f16 fsm[];
    const uint32_t sb = cvta_shared_u32(fsm);
    const uint32_t q_a  = sb;
    const uint32_t ck_a = sb + QSZ * 2;   // 2 bufs x {kh, kl, vh, vl}

    const int tid  = threadIdx.x;
    const int lane = tid & 31;
    const int wid  = tid >> 5;
    const int wrow  = wid & 3;     // row-tile (16 rows each)
    const int khalf = wid >> 2;    // key half of each chunk (0: keys 0-31, 1: 32-63)
    const int qr = lane >> 2, qc = lane & 3;
    const long bz = blockIdx.y;
    const long grow0 = bz * SS + blockIdx.x * 64;

    // ---- load Q tile (64 x 64 single limb) ----
#pragma unroll
    for (int i = 0; i < 2; i++) {
        int idx = tid + i * 256;
        int r = idx >> 3, s = idx & 7;
        long g = (grow0 + r) * 192 + s * 8;
        cp_async16(q_a + (uint32_t)(r * FAS + s * 8) * 2, qkvfh + g);
    }
    cp_commit();

    auto load_chunk = [&](int c, int buf) {
        const uint32_t base = ck_a + (uint32_t)buf * 4 * CSZ * 2;
#pragma unroll
        for (int i = 0; i < 2; i++) {
            int idx = tid + i * 256;
            int r = idx >> 3, s = idx & 7;
            long g = (bz * SS + c * 64 + r) * 192 + s * 8;
            uint32_t so = (uint32_t)(r * FAS + s * 8) * 2;
            cp_async16(base + so,               qkvfh + g + 64);    // k hi
            cp_async16(base + CSZ * 2 + so,     qkvfl + g + 64);    // k lo
            cp_async16(base + 2 * CSZ * 2 + so, qkvfh + g + 128);   // v hi
            cp_async16(base + 3 * CSZ * 2 + so, qkvfl + g + 128);   // v lo
        }
        cp_commit();
    };

    load_chunk(0, 0);
    cp_wait<1>();
    __syncthreads();

    // Q a-frags: 4 ksteps over d=64
    const uint32_t qa_off = (uint32_t)((lane & 15) + wrow * 16) * (FAS * 2) + (lane >> 4) * 16;
    uint32_t qa[4][4];
#pragma unroll
    for (int ks = 0; ks < 4; ks++)
        ldsm_x4(qa[ks][0], qa[ks][1], qa[ks][2], qa[ks][3], q_a + qa_off + ks * 32);

    const uint32_t kb_off = (uint32_t)(khalf * 32 + ((lane >> 4) & 1) * 8 + (lane & 7)) * (FAS * 2)
                            + ((lane >> 3) & 1) * 16;
    const uint32_t vb_off = (uint32_t)(khalf * 32 + (lane & 7) + ((lane >> 3) & 1) * 8) * (FAS * 2)
                            + ((lane >> 4) & 1) * 16;

    float o[8][4];
#pragma unroll
    for (int t = 0; t < 8; t++)
#pragma unroll
        for (int u = 0; u < 4; u++) o[t][u] = 0.f;
    float rs0 = 0.f, rs1 = 0.f;

    for (int c = 0; c < SS / 64; c++) {
        const int buf = c & 1;
        cp_wait<0>();
        __syncthreads();
        if (c + 1 < SS / 64) load_chunk(c + 1, buf ^ 1);

        const uint32_t kh_a = ck_a + (uint32_t)buf * 4 * CSZ * 2;
        const uint32_t kl_a = kh_a + CSZ * 2;
        const uint32_t vh_a = kh_a + 2 * CSZ * 2;
        const uint32_t vl_a = kh_a + 3 * CSZ * 2;

        // ---- S = q k^T over this warp's 32 keys (4 n8 tiles) ----
        float s[4][4];
#pragma unroll
        for (int j = 0; j < 4; j++)
#pragma unroll
            for (int u = 0; u < 4; u++) s[j][u] = 0.f;

#pragma unroll
        for (int ks = 0; ks < 4; ks++) {
            uint32_t kbh[4][2], kbl[4][2];
#pragma unroll
            for (int j4 = 0; j4 < 2; j4++) {
                uint32_t off = kb_off + (uint32_t)j4 * (16 * FAS * 2) + ks * 32;
                ldsm_x4(kbh[2*j4][0], kbh[2*j4][1], kbh[2*j4+1][0], kbh[2*j4+1][1], kh_a + off);
                ldsm_x4(kbl[2*j4][0], kbl[2*j4][1], kbl[2*j4+1][0], kbl[2*j4+1][1], kl_a + off);
            }
#pragma unroll
            for (int j = 0; j < 4; j++) {
                mma_f16(s[j], qa[ks], kbh[j]);
                mma_f16(s[j], qa[ks], kbl[j]);
            }
        }

        // ---- P = exp(alpha*S) single f16; C-frag -> A-frag (2 ksteps) ----
        uint32_t pa[2][4];
#pragma unroll
        for (int j = 0; j < 4; j++) {
            float p0 = __expf(s[j][0] * alpha);
            float p1 = __expf(s[j][1] * alpha);
            float p2 = __expf(s[j][2] * alpha);
            float p3 = __expf(s[j][3] * alpha);
            rs0 += p0 + p1;
            rs1 += p2 + p3;
            int ks2 = j >> 1, half = (j & 1) * 2;
            pa[ks2][half + 0] = pack_f16(p0, p1);
            pa[ks2][half + 1] = pack_f16(p2, p3);
        }

        // ---- O += P V (warp's 32 keys = 2 ksteps; 8 d-tiles) ----
#pragma unroll
        for (int ks = 0; ks < 2; ks++) {
            uint32_t vbh[8][2], vbl[8][2];
#pragma unroll
            for (int i = 0; i < 4; i++) {
                uint32_t off = vb_off + (uint32_t)ks * (16 * FAS * 2) + i * 32;
                ldsm_x4_t(vbh[2*i][0], vbh[2*i][1], vbh[2*i+1][0], vbh[2*i+1][1], vh_a + off);
                ldsm_x4_t(vbl[2*i][0], vbl[2*i][1], vbl[2*i+1][0], vbl[2*i+1][1], vl_a + off);
            }
#pragma unroll
            for (int t = 0; t < 8; t++) {
                mma_f16(o[t], pa[ks], vbh[t]);
                mma_f16(o[t], pa[ks], vbl[t]);
            }
        }
    }

    // ---- merge key-halves, normalize, store ----
    rs0 += __shfl_xor_sync(0xffffffffu, rs0, 1);
    rs0 += __shfl_xor_sync(0xffffffffu, rs0, 2);
    rs1 += __shfl_xor_sync(0xffffffffu, rs1, 1);
    rs1 += __shfl_xor_sync(0xffffffffu, rs1, 2);

    __syncthreads();   // all chunk smem reads done; safe to reuse
    float* sof = reinterpret_cast<float*>(fsm + QSZ);
    float4* sof4 = reinterpret_cast<float4*>(sof);
    float* zf = sof + 4 * 8 * 32 * 4;   // after 16KB of O partials

    if (wid >= 4) {
        int base = (wid - 4) * 256;
#pragma unroll
        for (int t = 0; t < 8; t++) {
            float4 v; v.x = o[t][0]; v.y = o[t][1]; v.z = o[t][2]; v.w = o[t][3];
            sof4[base + t * 32 + lane] = v;
        }
        if (qc == 0) {
            zf[(wid - 4) * 16 + qr]     = rs0;
            zf[(wid - 4) * 16 + qr + 8] = rs1;
        }
    }
    __syncthreads();
    if (wid < 4) {
        int base = wid * 256;
#pragma unroll
        for (int t = 0; t < 8; t++) {
            float4 v = sof4[base + t * 32 + lane];
            o[t][0] += v.x; o[t][1] += v.y; o[t][2] += v.z; o[t][3] += v.w;
        }
        rs0 += zf[wid * 16 + qr];
        rs1 += zf[wid * 16 + qr + 8];
        float inv0 = 1.0f / rs0;
        float inv1 = 1.0f / rs1;
        long g0 = grow0 + wid * 16 + qr;
#pragma unroll
        for (int t = 0; t < 8; t++) {
            int col = t * 8 + qc * 2;
            *reinterpret_cast<uint32_t*>(&headf[g0 * DKK + col]) =
                pack_f16(o[t][0] * inv0, o[t][1] * inv0);
            *reinterpret_cast<uint32_t*>(&headf[(g0 + 8) * DKK + col]) =
                pack_f16(o[t][2] * inv1, o[t][3] * inv1);
        }
    }
}

// ---------------------------------------------------------------------------
// Weight prep (all limbs x1024; hi-limb scale exact)
// ---------------------------------------------------------------------------
__device__ __forceinline__ void wsplit(float w, f16& oh, f16& ol) {
    f16 h = __float2half_rn(w);
    oh = __float2half_rn(__half2float(h) * 1024.0f);
    ol = __float2half_rn((w - __half2float(h)) * 1024.0f);
}

__global__ void transpose_split_f16(const float* __restrict__ in,
                                    f16* __restrict__ oh, f16* __restrict__ ol,
                                    int R, int C_) {
    __shared__ float tt[32][33];
    int r0 = blockIdx.y * 32, c0 = blockIdx.x * 32;
#pragma unroll
    for (int i = 0; i < 32; i += 8)
        tt[threadIdx.y + i][threadIdx.x] = in[(long)(r0 + threadIdx.y + i) * C_ + c0 + threadIdx.x];
    __syncthreads();
#pragma unroll
    for (int i = 0; i < 32; i += 8) {
        long o = (long)(c0 + threadIdx.y + i) * R + r0 + threadIdx.x;
        wsplit(tt[threadIdx.x][threadIdx.y + i], oh[o], ol[o]);
    }
}

__global__ void prep_qkvw(const float* __restrict__ Wq, const float* __restrict__ Wk,
                          const float* __restrict__ Wv, const float* __restrict__ bq,
                          const float* __restrict__ bk, const float* __restrict__ bv) {
    int idx = blockIdx.x * 256 + threadIdx.x;
    if (idx < 192 * DD) {
        int n = idx >> 9, k = idx & 511;
        const float* W = (n < 64) ? Wq : ((n < 128) ? Wk : Wv);
        float v = W[k * DKK + (n & 63)];
        wsplit(v, g_wqkvfh[idx], g_wqkvfl[idx]);
    }
    if (idx < 192) {
        g_bqkv[idx] = (idx < 64) ? bq[idx] : ((idx < 128) ? bk[idx - 64] : bv[idx - 128]);
    }
}

__global__ void prep_wo(const float* __restrict__ Wo) {
    int idx = blockIdx.x * 256 + threadIdx.x;
    if (idx >= DD * DKK) return;
    int e = idx / DKK, t = idx % DKK;
    float s = 0.f;
#pragma unroll
    for (int j = 0; j < 8; j++) s += Wo[(j * DKK + t) * DD + e];
    wsplit(s, g_wofh[idx], g_wofl[idx]);
}

// ---------------------------------------------------------------------------
// Embedding + positional encoding (fp16 pair out)
// ---------------------------------------------------------------------------
__global__ void embed_kernel(const int* __restrict__ ids, const float* __restrict__ emb) {
    long i2 = (long)blockIdx.x * 256 + threadIdx.x;
    if (i2 >= NTOT / 2) return;
    long e = i2 * 2;
    int d  = (int)(e & (DD - 1));
    int bs = (int)(e >> 9);
    int s  = bs & (SS - 1);
    int id = ids[bs];
    float v0 = 0.f, v1 = 0.f;
    if (id != 0) {
        const float* er = emb + (long)id * DD;
        v0 = er[d]; v1 = er[d + 1];
    }
    double f0 = pow(10000.0, (double)d / 256.0);
    double f1 = pow(10000.0, (double)(d + 1) / 256.0);
    v0 += sinf((float)((double)s / f0));
    v1 += cosf((float)((double)s / f1));
    uint32_t hp, lp;
    split_f16p(v0, v1, hp, lp);
    *reinterpret_cast<uint32_t*>(&g_xfh[e]) = hp;
    *reinterpret_cast<uint32_t*>(&g_xfl[e]) = lp;
}

// ---------------------------------------------------------------------------
// LayerNorm finalize + normalize
// ---------------------------------------------------------------------------
__global__ void finalize_kernel(int n) {
    __shared__ double ds[256], dq[256];
    double a = 0.0, b = 0.0;
    for (int i = threadIdx.x; i < n; i += 256) {
        a += (double)g_psum[i];
        b += (double)g_psq[i];
    }
    ds[threadIdx.x] = a; dq[threadIdx.x] = b; __syncthreads();
    for (int s = 128; s > 0; s >>= 1) {
        if (threadIdx.x < s) {
            ds[threadIdx.x] += ds[threadIdx.x + s];
            dq[threadIdx.x] += dq[threadIdx.x + s];
        }
        __syncthreads();
    }
    if (threadIdx.x == 0) {
        double m = ds[0] / (double)NTOT;
        double v = dq[0] / (double)NTOT - m * m;
        g_stats[0] = (float)m;
        g_stats[1] = (float)(1.0 / sqrt(v + 1e-5));
    }
}

__global__ void normalize_f16(const float* __restrict__ y,
                              f16* __restrict__ oh, f16* __restrict__ ol) {
    long i2 = (long)blockIdx.x * 256 + threadIdx.x;
    long e = i2 * 2;
    if (e >= NTOT) return;
    float m = g_stats[0], rs = g_stats[1];
    float2 yy = *reinterpret_cast<const float2*>(&y[e]);
    uint32_t hp, lp;
    split_f16p((yy.x - m) * rs, (yy.y - m) * rs, hp, lp);
    *reinterpret_cast<uint32_t*>(&oh[e]) = hp;
    *reinterpret_cast<uint32_t*>(&ol[e]) = lp;
}

__global__ void normalize_out(const float* __restrict__ y, float* __restrict__ out) {
    long i2 = (long)blockIdx.x * 256 + threadIdx.x;
    long e = i2 * 2;
    if (e >= NTOT) return;
    float m = g_stats[0], rs = g_stats[1];
    float2 yy = *reinterpret_cast<const float2*>(&y[e]);
    float2 o; o.x = (yy.x - m) * rs; o.y = (yy.y - m) * rs;
    *reinterpret_cast<float2*>(&out[e]) = o;
}

// ---------------------------------------------------------------------------
// Launch
// ---------------------------------------------------------------------------
extern "C" void kernel_launch(void* const* d_in, const int* in_sizes, int n_in,
                              void* d_out, int out_size)
{
    const int*   ids = (const int*)  d_in[0];
    const float* emb = (const float*)d_in[1];
    const float* Wq  = (const float*)d_in[2];
    const float* bq  = (const float*)d_in[3];
    const float* Wk  = (const float*)d_in[4];
    const float* bk  = (const float*)d_in[5];
    const float* Wv  = (const float*)d_in[6];
    const float* bv  = (const float*)d_in[7];
    const float* Wo  = (const float*)d_in[8];
    const float* bo  = (const float*)d_in[9];
    const float* W1  = (const float*)d_in[10];
    const float* b1  = (const float*)d_in[11];
    const float* W2  = (const float*)d_in[12];
    const float* b2  = (const float*)d_in[13];

    float *y, *bqkv, *psum, *psq;
    f16 *xfh, *xfl, *x1fh, *x1fl, *qkvfh, *qkvfl, *headf, *hf;
    f16 *wqkvfh, *wqkvfl, *wofh, *wofl, *w1fh, *w1fl, *w2fh, *w2fl;
    cudaGetSymbolAddress((void**)&y,      g_y);
    cudaGetSymbolAddress((void**)&xfh,    g_xfh);
    cudaGetSymbolAddress((void**)&xfl,    g_xfl);
    cudaGetSymbolAddress((void**)&x1fh,   g_x1fh);
    cudaGetSymbolAddress((void**)&x1fl,   g_x1fl);
    cudaGetSymbolAddress((void**)&qkvfh,  g_qkvfh);
    cudaGetSymbolAddress((void**)&qkvfl,  g_qkvfl);
    cudaGetSymbolAddress((void**)&headf,  g_headf);
    cudaGetSymbolAddress((void**)&hf,     g_hf);
    cudaGetSymbolAddress((void**)&wqkvfh, g_wqkvfh);
    cudaGetSymbolAddress((void**)&wqkvfl, g_wqkvfl);
    cudaGetSymbolAddress((void**)&wofh,   g_wofh);
    cudaGetSymbolAddress((void**)&wofl,   g_wofl);
    cudaGetSymbolAddress((void**)&w1fh,   g_w1fh);
    cudaGetSymbolAddress((void**)&w1fl,   g_w1fl);
    cudaGetSymbolAddress((void**)&w2fh,   g_w2fh);
    cudaGetSymbolAddress((void**)&w2fl,   g_w2fl);
    cudaGetSymbolAddress((void**)&bqkv,   g_bqkv);
    cudaGetSymbolAddress((void**)&psum,   g_psum);
    cudaGetSymbolAddress((void**)&psq,    g_psq);

    const int SM128 = 3 * (128 + 256) * SMSB * 2;   // 92160
    const int SM64  = 3 * (128 + 128) * SMSB * 2;   // 61440
    const int SMFA  = (64 * FAS + 8 * 64 * FAS) * 2; // 82944

    cudaFuncSetAttribute((const void*)gemm2<64, 32, 32, 2>,
                         cudaFuncAttributeMaxDynamicSharedMemorySize, SM64);
    cudaFuncSetAttribute((const void*)gemm2<128, 64, 32, 0>,
                         cudaFuncAttributeMaxDynamicSharedMemorySize, SM128);
    cudaFuncSetAttribute((const void*)gemm2<128, 64, 32, 1>,
                         cudaFuncAttributeMaxDynamicSharedMemorySize, SM128);
    cudaFuncSetAttribute((const void*)flash_attn,
                         cudaFuncAttributeMaxDynamicSharedMemorySize, SMFA);

    const float inv_div = 1.0f / 32.0f;
    const float inv_ws  = 1.0f / 1024.0f;
    dim3 tb(32, 8);

    // ---- weight prep ----
    prep_qkvw<<<(192 * DD + 255) / 256, 256>>>(Wq, Wk, Wv, bq, bk, bv);
    prep_wo<<<(DD * DKK + 255) / 256, 256>>>(Wo);
    transpose_split_f16<<<dim3(DFFN / 32, DD / 32), tb>>>(W1, w1fh, w1fl, DD, DFFN);
    transpose_split_f16<<<dim3(DD / 32, DFFN / 32), tb>>>(W2, w2fh, w2fl, DFFN, DD);

    embed_kernel<<<NTOT / 512, 256>>>(ids, emb);

    for (int it = 0; it < NREP; it++) {
        // QKV: x @ wqkv^T + bqkv -> qkv f16 pair [16384,192]
        gemm2<64, 32, 32, 2><<<dim3(3, 128, 1), 256, SM64>>>(
            xfh, DD, wqkvfh, wqkvfl, DD, bqkv, 0, 0,
            0, qkvfh, qkvfl, 192, DD, inv_ws, 0, 0);

        // flash attention: head = softmax(q k^T / 32) v -> f16 single
        flash_attn<<<dim3(SS / 64, BB), 256, SMFA>>>(qkvfh, qkvfl, headf, inv_div);

        // y = head @ Wo_eff + bo + x, LN partials
        gemm2<128, 64, 32, 0><<<dim3(4, 128, 1), 256, SM128>>>(
            headf, DKK, wofh, wofl, DKK, bo, xfh, xfl,
            y, 0, 0, DD, DKK, inv_ws, psum, psq);

        finalize_kernel<<<1, 256>>>(512);
        normalize_f16<<<NTOT / 512, 256>>>(y, x1fh, x1fl);

        // h = relu(x1 @ W1 + b1) -> f16 single
        gemm2<128, 64, 32, 1><<<dim3(16, 128, 1), 256, SM128>>>(
            x1fh, DD, w1fh, w1fl, DD, b1, 0, 0,
            0, hf, 0, DFFN, DD, inv_ws, 0, 0);

        // y = h @ W2 + b2 + x1, LN partials
        gemm2<128, 64, 32, 0><<<dim3(4, 128, 1), 256, SM128>>>(
            hf, DFFN, w2fh, w2fl, DFFN, b2, x1fh, x1fl,
            y, 0, 0, DD, DFFN, inv_ws, psum, psq);

        finalize_kernel<<<1, 256>>>(512);
        if (it == NREP - 1)
            normalize_out<<<NTOT / 512, 256>>>(y, (float*)d_out);
        else
            normalize_f16<<<NTOT / 512, 256>>>(y, xfh, xfl);
    }
}

// round 11
// speedup vs baseline: 2.3961x; 1.0106x over previous
#include <cuda_runtime.h>
#include <cuda_fp16.h>
#include <math.h>
#include <stdint.h>

#define BB   8
#define SS   2048
#define DD   512
#define DKK  64
#define DFFN 2048
#define NREP 6
#define MSROWS (BB*SS)          // 16384
#define NTOT (BB*SS*DD)         // 8388608

typedef __half f16;

// ---------------------------------------------------------------------------
// Scratch (all fp16; y streams stored as f16 hi/lo pairs)
// ---------------------------------------------------------------------------
__device__ f16 g_xfh [NTOT];    // y2 pair (post-attn-block stream / embed at it 0)
__device__ f16 g_xfl [NTOT];
__device__ f16 g_x1fh[NTOT];    // y1 pair (post-attention, pre-mid-LN stream)
__device__ f16 g_x1fl[NTOT];
__device__ f16 g_qkvfh[MSROWS*192];
__device__ f16 g_qkvfl[MSROWS*192];
__device__ f16 g_headf[MSROWS*DKK];
__device__ f16 g_hf[(long)MSROWS*DFFN];

__device__ f16 g_wqkvfh[192*DD];
__device__ f16 g_wqkvfl[192*DD];
__device__ f16 g_wofh[DD*DKK];
__device__ f16 g_wofl[DD*DKK];
__device__ f16 g_w1fh[DFFN*DD];
__device__ f16 g_w1fl[DFFN*DD];
__device__ f16 g_w2fh[DD*DFFN];
__device__ f16 g_w2fl[DD*DFFN];
__device__ float g_bqkv[192];
__device__ float g_rsqkv[192];      // rowsum of combined QKV weight over k
__device__ float g_rsw1[DFFN];      // colsum of W1

__device__ float g_psum[1024];
__device__ float g_psq [1024];
__device__ float g_statsA[2];       // mid-LN (m, rs)
__device__ float g_statsB[2];       // post-LN (m, rs); seeded {0,1} by embed
__device__ float g_dummy0[2];

// ---------------------------------------------------------------------------
// Helpers
// ---------------------------------------------------------------------------
__device__ __forceinline__ uint32_t cvta_shared_u32(const void* p) {
    uint32_t a;
    asm("{ .reg .u64 t; cvta.to.shared.u64 t, %1; cvt.u32.u64 %0, t; }" : "=r"(a) : "l"(p));
    return a;
}
__device__ __forceinline__ void cp_async16(uint32_t saddr, const void* gptr) {
    asm volatile("cp.async.cg.shared.global [%0], [%1], 16;" :: "r"(saddr), "l"(gptr));
}
__device__ __forceinline__ void cp_commit() {
    asm volatile("cp.async.commit_group;" ::: "memory");
}
template<int N>
__device__ __forceinline__ void cp_wait() {
    asm volatile("cp.async.wait_group %0;" :: "n"(N) : "memory");
}
__device__ __forceinline__ void ldsm_x4(uint32_t& r0, uint32_t& r1, uint32_t& r2, uint32_t& r3,
                                        uint32_t addr) {
    asm volatile("ldmatrix.sync.aligned.m8n8.x4.shared.b16 {%0,%1,%2,%3}, [%4];"
                 : "=r"(r0), "=r"(r1), "=r"(r2), "=r"(r3) : "r"(addr));
}
__device__ __forceinline__ void ldsm_x4_t(uint32_t& r0, uint32_t& r1, uint32_t& r2, uint32_t& r3,
                                          uint32_t addr) {
    asm volatile("ldmatrix.sync.aligned.m8n8.x4.trans.shared.b16 {%0,%1,%2,%3}, [%4];"
                 : "=r"(r0), "=r"(r1), "=r"(r2), "=r"(r3) : "r"(addr));
}
__device__ __forceinline__ uint32_t pack_f16(float e0, float e1) {
    uint32_t r;
    asm("cvt.rn.f16x2.f32 %0, %1, %2;" : "=r"(r) : "f"(e1), "f"(e0));
    return r;
}
__device__ __forceinline__ void split_f16p(float e0, float e1, uint32_t& hi, uint32_t& lo) {
    f16 h0 = __float2half_rn(e0);
    f16 h1 = __float2half_rn(e1);
    float l0 = e0 - __half2float(h0);
    float l1 = e1 - __half2float(h1);
    hi = ((uint32_t)__half_as_ushort(h1) << 16) | __half_as_ushort(h0);
    lo = pack_f16(l0, l1);
}
__device__ __forceinline__ void mma_f16(float* c, const uint32_t* a, const uint32_t* b) {
    asm volatile(
        "mma.sync.aligned.m16n8k16.row.col.f32.f16.f16.f32 "
        "{%0,%1,%2,%3}, {%4,%5,%6,%7}, {%8,%9}, {%0,%1,%2,%3};"
        : "+f"(c[0]), "+f"(c[1]), "+f"(c[2]), "+f"(c[3])
        : "r"(a[0]), "r"(a[1]), "r"(a[2]), "r"(a[3]), "r"(b[0]), "r"(b[1]));
}

#define SMSB 40

// ---------------------------------------------------------------------------
// Unified 2-term fp16 GEMM with LN folding.
//   raw = acc * alpha  (alpha folds the x1024 weight prescale)
// MODE 0: v = raw + bias + (srch+srcl - m_res)*rs_res   [residual from y-pair]
//         -> Cf/Cfl pair + LN partials
// MODE 1: v = (raw - m_in*rowsum[col])*rs_in + bias, ReLU -> Cf single
// MODE 2: v = (raw - m_in*rowsum[col])*rs_in + bias -> Cf/Cfl pair
// ---------------------------------------------------------------------------
template<int BN, int WM, int WN, int MODE>
__global__ void __launch_bounds__(256, 2)
gemm2(const f16* __restrict__ Af, int lda,
      const f16* __restrict__ Bh, const f16* __restrict__ Bl, int ldb,
      const float* __restrict__ bias,
      const float* __restrict__ instats, const float* __restrict__ rowsum,
      const f16* __restrict__ srch, const f16* __restrict__ srcl,
      const float* __restrict__ resstats,
      f16* __restrict__ Cf, f16* __restrict__ Cfl,
      int ldc, int K, float alpha,
      float* __restrict__ psum, float* __restrict__ psq)
{
    constexpr int MT = WM / 16;
    constexpr int NT = WN / 8;
    constexpr int WARPS_N = BN / WN;
    static_assert((128 / WM) * (BN / WN) == 8, "8 warps");
    static_assert(NT % 2 == 0, "NT even");
    constexpr int STAGES = 3;
    constexpr int OFF_BH = 128 * SMSB;
    constexpr int OFF_BL = OFF_BH + BN * SMSB;
    constexpr int BUFSZ  = OFF_BL + BN * SMSB;
    constexpr int BITER  = (BN * 4) / 256;

    extern __shared__ f16 smemf[];
    __shared__ float s_red0[256];
    __shared__ float s_red1[256];

    const int tid  = threadIdx.x;
    const int lane = tid & 31;
    const int wid  = tid >> 5;
    const int warp_m = wid / WARPS_N;
    const int warp_n = wid % WARPS_N;
    const int qr = lane >> 2;
    const int qc = lane & 3;

    const int m0 = blockIdx.y * 128;
    const int n0 = blockIdx.x * BN;

    float acc[MT][NT][4];
#pragma unroll
    for (int i = 0; i < MT; i++)
#pragma unroll
        for (int j = 0; j < NT; j++)
#pragma unroll
            for (int u = 0; u < 4; u++) acc[i][j][u] = 0.f;

    const uint32_t sb = cvta_shared_u32(smemf);

    auto load_chunk = [&](int c, int stg) {
        const int k0 = c << 5;
        const uint32_t base = sb + (uint32_t)stg * (BUFSZ * 2);
#pragma unroll
        for (int i = 0; i < 2; i++) {
            int idx = tid + i * 256;
            int row = idx >> 2, c8 = idx & 3;
            long g = (long)(m0 + row) * lda + k0 + c8 * 8;
            uint32_t so = (uint32_t)(row * SMSB + c8 * 8) * 2;
            cp_async16(base + so, Af + g);
        }
#pragma unroll
        for (int i = 0; i < BITER; i++) {
            int idx = tid + i * 256;
            int row = idx >> 2, c8 = idx & 3;
            long g = (long)(n0 + row) * ldb + k0 + c8 * 8;
            uint32_t so = (uint32_t)(row * SMSB + c8 * 8) * 2;
            cp_async16(base + OFF_BH * 2 + so, Bh + g);
            cp_async16(base + OFF_BL * 2 + so, Bl + g);
        }
    };

    const int nch = K >> 5;
#pragma unroll
    for (int s = 0; s < STAGES - 1; s++) { load_chunk(s, s); cp_commit(); }

    const uint32_t a_off = (uint32_t)(((lane & 15) + warp_m * WM) * SMSB + (lane >> 4) * 8) * 2;
    const uint32_t b_off = (uint32_t)((((lane >> 4) & 1) * 8 + (lane & 7) + warp_n * WN) * SMSB
                                      + ((lane >> 3) & 1) * 8) * 2;

    for (int c = 0; c < nch; c++) {
        const int stg = c % STAGES;
        if (c + STAGES - 1 < nch) {
            load_chunk(c + STAGES - 1, (c + STAGES - 1) % STAGES);
            cp_commit();
            cp_wait<STAGES - 1>();
        } else {
            cp_wait<0>();
        }
        __syncthreads();

        const uint32_t stA  = sb + (uint32_t)stg * (BUFSZ * 2);
        const uint32_t stBh = stA + OFF_BH * 2;
        const uint32_t stBl = stA + OFF_BL * 2;

#pragma unroll
        for (int ks = 0; ks < 2; ks++) {
            const uint32_t kk2 = (uint32_t)ks * 32;
            uint32_t bh[NT][2], bl[NT][2];
#pragma unroll
            for (int in2 = 0; in2 < NT / 2; in2++) {
                uint32_t off = b_off + (uint32_t)in2 * (16 * SMSB * 2) + kk2;
                ldsm_x4(bh[2*in2][0], bh[2*in2][1], bh[2*in2+1][0], bh[2*in2+1][1], stBh + off);
                ldsm_x4(bl[2*in2][0], bl[2*in2][1], bl[2*in2+1][0], bl[2*in2+1][1], stBl + off);
            }
#pragma unroll
            for (int im = 0; im < MT; im++) {
                uint32_t off = a_off + (uint32_t)im * (16 * SMSB * 2) + kk2;
                uint32_t ah[4];
                ldsm_x4(ah[0], ah[1], ah[2], ah[3], stA + off);
#pragma unroll
                for (int in_ = 0; in_ < NT; in_++) {
                    mma_f16(acc[im][in_], ah, bh[in_]);
                    mma_f16(acc[im][in_], ah, bl[in_]);
                }
            }
        }
        __syncthreads();
    }

    // ---- epilogue ----
    float m_in = 0.f, rs_in = 1.f, m_res = 0.f, rs_res = 1.f;
    if (MODE == 1 || MODE == 2) { m_in = instats[0]; rs_in = instats[1]; }
    if (MODE == 0) { m_res = resstats[0]; rs_res = resstats[1]; }

    float lsum = 0.f, lsq = 0.f;
#pragma unroll
    for (int im = 0; im < MT; im++) {
#pragma unroll
        for (int h2 = 0; h2 < 2; h2++) {
            const int row = m0 + warp_m * WM + im * 16 + qr + h2 * 8;
#pragma unroll
            for (int in_ = 0; in_ < NT; in_++) {
                const int col = n0 + warp_n * WN + in_ * 8 + qc * 2;
                float raw0 = acc[im][in_][h2 * 2 + 0] * alpha;
                float raw1 = acc[im][in_][h2 * 2 + 1] * alpha;
                if (MODE == 0) {
                    long si = (long)row * ldc + col;
                    float y0 = __half2float(srch[si])     + __half2float(srcl[si]);
                    float y1 = __half2float(srch[si + 1]) + __half2float(srcl[si + 1]);
                    float v0 = raw0 + bias[col]     + (y0 - m_res) * rs_res;
                    float v1 = raw1 + bias[col + 1] + (y1 - m_res) * rs_res;
                    uint32_t hp, lp;
                    split_f16p(v0, v1, hp, lp);
                    *reinterpret_cast<uint32_t*>(&Cf [(long)row * ldc + col]) = hp;
                    *reinterpret_cast<uint32_t*>(&Cfl[(long)row * ldc + col]) = lp;
                    lsum += v0 + v1;
                    lsq  += v0 * v0 + v1 * v1;
                } else {
                    float v0 = (raw0 - m_in * rowsum[col])     * rs_in + bias[col];
                    float v1 = (raw1 - m_in * rowsum[col + 1]) * rs_in + bias[col + 1];
                    if (MODE == 1) {
                        v0 = fmaxf(v0, 0.f); v1 = fmaxf(v1, 0.f);
                        *reinterpret_cast<uint32_t*>(&Cf[(long)row * ldc + col]) = pack_f16(v0, v1);
                    } else {
                        uint32_t hp, lp;
                        split_f16p(v0, v1, hp, lp);
                        *reinterpret_cast<uint32_t*>(&Cf [(long)row * ldc + col]) = hp;
                        *reinterpret_cast<uint32_t*>(&Cfl[(long)row * ldc + col]) = lp;
                    }
                }
            }
        }
    }

    if (MODE == 0) {
        s_red0[tid] = lsum; s_red1[tid] = lsq;
        __syncthreads();
        for (int s = 128; s > 0; s >>= 1) {
            if (tid < s) { s_red0[tid] += s_red0[tid + s]; s_red1[tid] += s_red1[tid + s]; }
            __syncthreads();
        }
        if (tid == 0) {
            int cta = blockIdx.y * gridDim.x + blockIdx.x;
            psum[cta] = s_red0[0];
            psq [cta] = s_red1[0];
        }
    }
}

// ---------------------------------------------------------------------------
// Flash attention (2-term fp16, 64 q-rows/CTA, 2 key-half warps) — validated R10
// ---------------------------------------------------------------------------
#define FAS 72

__global__ void __launch_bounds__(256, 2)
flash_attn(const f16* __restrict__ qkvfh, const f16* __restrict__ qkvfl,
           f16* __restrict__ headf, float alpha)
{
    constexpr int QSZ = 64 * FAS;
    constexpr int CSZ = 64 * FAS;

    extern __shared__ f16 fsm[];
    const uint32_t sb = cvta_shared_u32(fsm);
    const uint32_t q_a  = sb;
    const uint32_t ck_a = sb + QSZ * 2;

    const int tid  = threadIdx.x;
    const int lane = tid & 31;
    const int wid  = tid >> 5;
    const int wrow  = wid & 3;
    const int khalf = wid >> 2;
    const int qr = lane >> 2, qc = lane & 3;
    const long bz = blockIdx.y;
    const long grow0 = bz * SS + blockIdx.x * 64;

#pragma unroll
    for (int i = 0; i < 2; i++) {
        int idx = tid + i * 256;
        int r = idx >> 3, s = idx & 7;
        long g = (grow0 + r) * 192 + s * 8;
        cp_async16(q_a + (uint32_t)(r * FAS + s * 8) * 2, qkvfh + g);
    }
    cp_commit();

    auto load_chunk = [&](int c, int buf) {
        const uint32_t base = ck_a + (uint32_t)buf * 4 * CSZ * 2;
#pragma unroll
        for (int i = 0; i < 2; i++) {
            int idx = tid + i * 256;
            int r = idx >> 3, s = idx & 7;
            long g = (bz * SS + c * 64 + r) * 192 + s * 8;
            uint32_t so = (uint32_t)(r * FAS + s * 8) * 2;
            cp_async16(base + so,               qkvfh + g + 64);
            cp_async16(base + CSZ * 2 + so,     qkvfl + g + 64);
            cp_async16(base + 2 * CSZ * 2 + so, qkvfh + g + 128);
            cp_async16(base + 3 * CSZ * 2 + so, qkvfl + g + 128);
        }
        cp_commit();
    };

    load_chunk(0, 0);
    cp_wait<1>();
    __syncthreads();

    const uint32_t qa_off = (uint32_t)((lane & 15) + wrow * 16) * (FAS * 2) + (lane >> 4) * 16;
    uint32_t qa[4][4];
#pragma unroll
    for (int ks = 0; ks < 4; ks++)
        ldsm_x4(qa[ks][0], qa[ks][1], qa[ks][2], qa[ks][3], q_a + qa_off + ks * 32);

    const uint32_t kb_off = (uint32_t)(khalf * 32 + ((lane >> 4) & 1) * 8 + (lane & 7)) * (FAS * 2)
                            + ((lane >> 3) & 1) * 16;
    const uint32_t vb_off = (uint32_t)(khalf * 32 + (lane & 7) + ((lane >> 3) & 1) * 8) * (FAS * 2)
                            + ((lane >> 4) & 1) * 16;

    float o[8][4];
#pragma unroll
    for (int t = 0; t < 8; t++)
#pragma unroll
        for (int u = 0; u < 4; u++) o[t][u] = 0.f;
    float rs0 = 0.f, rs1 = 0.f;

    for (int c = 0; c < SS / 64; c++) {
        const int buf = c & 1;
        cp_wait<0>();
        __syncthreads();
        if (c + 1 < SS / 64) load_chunk(c + 1, buf ^ 1);

        const uint32_t kh_a = ck_a + (uint32_t)buf * 4 * CSZ * 2;
        const uint32_t kl_a = kh_a + CSZ * 2;
        const uint32_t vh_a = kh_a + 2 * CSZ * 2;
        const uint32_t vl_a = kh_a + 3 * CSZ * 2;

        float s[4][4];
#pragma unroll
        for (int j = 0; j < 4; j++)
#pragma unroll
            for (int u = 0; u < 4; u++) s[j][u] = 0.f;

#pragma unroll
        for (int ks = 0; ks < 4; ks++) {
            uint32_t kbh[4][2], kbl[4][2];
#pragma unroll
            for (int j4 = 0; j4 < 2; j4++) {
                uint32_t off = kb_off + (uint32_t)j4 * (16 * FAS * 2) + ks * 32;
                ldsm_x4(kbh[2*j4][0], kbh[2*j4][1], kbh[2*j4+1][0], kbh[2*j4+1][1], kh_a + off);
                ldsm_x4(kbl[2*j4][0], kbl[2*j4][1], kbl[2*j4+1][0], kbl[2*j4+1][1], kl_a + off);
            }
#pragma unroll
            for (int j = 0; j < 4; j++) {
                mma_f16(s[j], qa[ks], kbh[j]);
                mma_f16(s[j], qa[ks], kbl[j]);
            }
        }

        uint32_t pa[2][4];
#pragma unroll
        for (int j = 0; j < 4; j++) {
            float p0 = __expf(s[j][0] * alpha);
            float p1 = __expf(s[j][1] * alpha);
            float p2 = __expf(s[j][2] * alpha);
            float p3 = __expf(s[j][3] * alpha);
            rs0 += p0 + p1;
            rs1 += p2 + p3;
            int ks2 = j >> 1, half = (j & 1) * 2;
            pa[ks2][half + 0] = pack_f16(p0, p1);
            pa[ks2][half + 1] = pack_f16(p2, p3);
        }

#pragma unroll
        for (int ks = 0; ks < 2; ks++) {
            uint32_t vbh[8][2], vbl[8][2];
#pragma unroll
            for (int i = 0; i < 4; i++) {
                uint32_t off = vb_off + (uint32_t)ks * (16 * FAS * 2) + i * 32;
                ldsm_x4_t(vbh[2*i][0], vbh[2*i][1], vbh[2*i+1][0], vbh[2*i+1][1], vh_a + off);
                ldsm_x4_t(vbl[2*i][0], vbl[2*i][1], vbl[2*i+1][0], vbl[2*i+1][1], vl_a + off);
            }
#pragma unroll
            for (int t = 0; t < 8; t++) {
                mma_f16(o[t], pa[ks], vbh[t]);
                mma_f16(o[t], pa[ks], vbl[t]);
            }
        }
    }

    rs0 += __shfl_xor_sync(0xffffffffu, rs0, 1);
    rs0 += __shfl_xor_sync(0xffffffffu, rs0, 2);
    rs1 += __shfl_xor_sync(0xffffffffu, rs1, 1);
    rs1 += __shfl_xor_sync(0xffffffffu, rs1, 2);

    __syncthreads();
    float* sof = reinterpret_cast<float*>(fsm + QSZ);
    float4* sof4 = reinterpret_cast<float4*>(sof);
    float* zf = sof + 4 * 8 * 32 * 4;

    if (wid >= 4) {
        int base = (wid - 4) * 256;
#pragma unroll
        for (int t = 0; t < 8; t++) {
            float4 v; v.x = o[t][0]; v.y = o[t][1]; v.z = o[t][2]; v.w = o[t][3];
            sof4[base + t * 32 + lane] = v;
        }
        if (qc == 0) {
            zf[(wid - 4) * 16 + qr]     = rs0;
            zf[(wid - 4) * 16 + qr + 8] = rs1;
        }
    }
    __syncthreads();
    if (wid < 4) {
        int base = wid * 256;
#pragma unroll
        for (int t = 0; t < 8; t++) {
            float4 v = sof4[base + t * 32 + lane];
            o[t][0] += v.x; o[t][1] += v.y; o[t][2] += v.z; o[t][3] += v.w;
        }
        rs0 += zf[wid * 16 + qr];
        rs1 += zf[wid * 16 + qr + 8];
        float inv0 = 1.0f / rs0;
        float inv1 = 1.0f / rs1;
        long g0 = grow0 + wid * 16 + qr;
#pragma unroll
        for (int t = 0; t < 8; t++) {
            int col = t * 8 + qc * 2;
            *reinterpret_cast<uint32_t*>(&headf[g0 * DKK + col]) =
                pack_f16(o[t][0] * inv0, o[t][1] * inv0);
            *reinterpret_cast<uint32_t*>(&headf[(g0 + 8) * DKK + col]) =
                pack_f16(o[t][2] * inv1, o[t][3] * inv1);
        }
    }
}

// ---------------------------------------------------------------------------
// Weight prep
// ---------------------------------------------------------------------------
__device__ __forceinline__ void wsplit(float w, f16& oh, f16& ol) {
    f16 h = __float2half_rn(w);
    oh = __float2half_rn(__half2float(h) * 1024.0f);
    ol = __float2half_rn((w - __half2float(h)) * 1024.0f);
}

__global__ void transpose_split_f16(const float* __restrict__ in,
                                    f16* __restrict__ oh, f16* __restrict__ ol,
                                    int R, int C_) {
    __shared__ float tt[32][33];
    int r0 = blockIdx.y * 32, c0 = blockIdx.x * 32;
#pragma unroll
    for (int i = 0; i < 32; i += 8)
        tt[threadIdx.y + i][threadIdx.x] = in[(long)(r0 + threadIdx.y + i) * C_ + c0 + threadIdx.x];
    __syncthreads();
#pragma unroll
    for (int i = 0; i < 32; i += 8) {
        long o = (long)(c0 + threadIdx.y + i) * R + r0 + threadIdx.x;
        wsplit(tt[threadIdx.x][threadIdx.y + i], oh[o], ol[o]);
    }
}

// colsum over leading dim: out[n] = sum_k W[k*N + n]
__global__ void colsum_kernel(const float* __restrict__ W, float* __restrict__ out,
                              int K, int N) {
    int n = blockIdx.x * 256 + threadIdx.x;
    if (n >= N) return;
    float s = 0.f;
    for (int k = 0; k < K; k++) s += W[(long)k * N + n];
    out[n] = s;
}

__global__ void prep_qkvw(const float* __restrict__ Wq, const float* __restrict__ Wk,
                          const float* __restrict__ Wv, const float* __restrict__ bq,
                          const float* __restrict__ bk, const float* __restrict__ bv) {
    int idx = blockIdx.x * 256 + threadIdx.x;
    if (idx < 192 * DD) {
        int n = idx >> 9, k = idx & 511;
        const float* W = (n < 64) ? Wq : ((n < 128) ? Wk : Wv);
        float v = W[k * DKK + (n & 63)];
        wsplit(v, g_wqkvfh[idx], g_wqkvfl[idx]);
    }
    if (idx < 192) {
        g_bqkv[idx] = (idx < 64) ? bq[idx] : ((idx < 128) ? bk[idx - 64] : bv[idx - 128]);
        const float* W = (idx < 64) ? Wq : ((idx < 128) ? Wk : Wv);
        float s = 0.f;
        for (int k = 0; k < DD; k++) s += W[k * DKK + (idx & 63)];
        g_rsqkv[idx] = s;
    }
}

__global__ void prep_wo(const float* __restrict__ Wo) {
    int idx = blockIdx.x * 256 + threadIdx.x;
    if (idx >= DD * DKK) return;
    int e = idx / DKK, t = idx % DKK;
    float s = 0.f;
#pragma unroll
    for (int j = 0; j < 8; j++) s += Wo[(j * DKK + t) * DD + e];
    wsplit(s, g_wofh[idx], g_wofl[idx]);
}

// ---------------------------------------------------------------------------
// Embedding + positional encoding -> y2 pair; seeds identity stats
// ---------------------------------------------------------------------------
__global__ void embed_kernel(const int* __restrict__ ids, const float* __restrict__ emb) {
    long i2 = (long)blockIdx.x * 256 + threadIdx.x;
    if (blockIdx.x == 0 && threadIdx.x == 0) {
        g_statsB[0] = 0.0f;
        g_statsB[1] = 1.0f;
    }
    if (i2 >= NTOT / 2) return;
    long e = i2 * 2;
    int d  = (int)(e & (DD - 1));
    int bs = (int)(e >> 9);
    int s  = bs & (SS - 1);
    int id = ids[bs];
    float v0 = 0.f, v1 = 0.f;
    if (id != 0) {
        const float* er = emb + (long)id * DD;
        v0 = er[d]; v1 = er[d + 1];
    }
    double f0 = pow(10000.0, (double)d / 256.0);
    double f1 = pow(10000.0, (double)(d + 1) / 256.0);
    v0 += sinf((float)((double)s / f0));
    v1 += cosf((float)((double)s / f1));
    uint32_t hp, lp;
    split_f16p(v0, v1, hp, lp);
    *reinterpret_cast<uint32_t*>(&g_xfh[e]) = hp;
    *reinterpret_cast<uint32_t*>(&g_xfl[e]) = lp;
}

// ---------------------------------------------------------------------------
// LayerNorm finalize: partials -> (m, rs) into the given slot
// ---------------------------------------------------------------------------
__global__ void finalize_kernel(int n, float* __restrict__ stats_out) {
    __shared__ double ds[256], dq[256];
    double a = 0.0, b = 0.0;
    for (int i = threadIdx.x; i < n; i += 256) {
        a += (double)g_psum[i];
        b += (double)g_psq[i];
    }
    ds[threadIdx.x] = a; dq[threadIdx.x] = b; __syncthreads();
    for (int s = 128; s > 0; s >>= 1) {
        if (threadIdx.x < s) {
            ds[threadIdx.x] += ds[threadIdx.x + s];
            dq[threadIdx.x] += dq[threadIdx.x + s];
        }
        __syncthreads();
    }
    if (threadIdx.x == 0) {
        double m = ds[0] / (double)NTOT;
        double v = dq[0] / (double)NTOT - m * m;
        stats_out[0] = (float)m;
        stats_out[1] = (float)(1.0 / sqrt(v + 1e-5));
    }
}

// final output: out = (yh + yl - m) * rs  (fp32)
__global__ void normalize_out(const f16* __restrict__ yh, const f16* __restrict__ yl,
                              const float* __restrict__ stats, float* __restrict__ out) {
    long i2 = (long)blockIdx.x * 256 + threadIdx.x;
    long e = i2 * 2;
    if (e >= NTOT) return;
    float m = stats[0], rs = stats[1];
    float y0 = __half2float(yh[e])     + __half2float(yl[e]);
    float y1 = __half2float(yh[e + 1]) + __half2float(yl[e + 1]);
    float2 o; o.x = (y0 - m) * rs; o.y = (y1 - m) * rs;
    *reinterpret_cast<float2*>(&out[e]) = o;
}

// ---------------------------------------------------------------------------
// Launch
// ---------------------------------------------------------------------------
extern "C" void kernel_launch(void* const* d_in, const int* in_sizes, int n_in,
                              void* d_out, int out_size)
{
    const int*   ids = (const int*)  d_in[0];
    const float* emb = (const float*)d_in[1];
    const float* Wq  = (const float*)d_in[2];
    const float* bq  = (const float*)d_in[3];
    const float* Wk  = (const float*)d_in[4];
    const float* bk  = (const float*)d_in[5];
    const float* Wv  = (const float*)d_in[6];
    const float* bv  = (const float*)d_in[7];
    const float* Wo  = (const float*)d_in[8];
    const float* bo  = (const float*)d_in[9];
    const float* W1  = (const float*)d_in[10];
    const float* b1  = (const float*)d_in[11];
    const float* W2  = (const float*)d_in[12];
    const float* b2  = (const float*)d_in[13];

    float *bqkv, *psum, *psq, *statsA, *statsB, *rsqkv, *rsw1;
    f16 *xfh, *xfl, *x1fh, *x1fl, *qkvfh, *qkvfl, *headf, *hf;
    f16 *wqkvfh, *wqkvfl, *wofh, *wofl, *w1fh, *w1fl, *w2fh, *w2fl;
    cudaGetSymbolAddress((void**)&xfh,    g_xfh);
    cudaGetSymbolAddress((void**)&xfl,    g_xfl);
    cudaGetSymbolAddress((void**)&x1fh,   g_x1fh);
    cudaGetSymbolAddress((void**)&x1fl,   g_x1fl);
    cudaGetSymbolAddress((void**)&qkvfh,  g_qkvfh);
    cudaGetSymbolAddress((void**)&qkvfl,  g_qkvfl);
    cudaGetSymbolAddress((void**)&headf,  g_headf);
    cudaGetSymbolAddress((void**)&hf,     g_hf);
    cudaGetSymbolAddress((void**)&wqkvfh, g_wqkvfh);
    cudaGetSymbolAddress((void**)&wqkvfl, g_wqkvfl);
    cudaGetSymbolAddress((void**)&wofh,   g_wofh);
    cudaGetSymbolAddress((void**)&wofl,   g_wofl);
    cudaGetSymbolAddress((void**)&w1fh,   g_w1fh);
    cudaGetSymbolAddress((void**)&w1fl,   g_w1fl);
    cudaGetSymbolAddress((void**)&w2fh,   g_w2fh);
    cudaGetSymbolAddress((void**)&w2fl,   g_w2fl);
    cudaGetSymbolAddress((void**)&bqkv,   g_bqkv);
    cudaGetSymbolAddress((void**)&rsqkv,  g_rsqkv);
    cudaGetSymbolAddress((void**)&rsw1,   g_rsw1);
    cudaGetSymbolAddress((void**)&psum,   g_psum);
    cudaGetSymbolAddress((void**)&psq,    g_psq);
    cudaGetSymbolAddress((void**)&statsA, g_statsA);
    cudaGetSymbolAddress((void**)&statsB, g_statsB);

    const int SM128 = 3 * (128 + 256) * SMSB * 2;    // 92160
    const int SM64  = 3 * (128 + 128) * SMSB * 2;    // 61440
    const int SMFA  = (64 * FAS + 8 * 64 * FAS) * 2; // 82944

    cudaFuncSetAttribute((const void*)gemm2<64, 32, 32, 2>,
                         cudaFuncAttributeMaxDynamicSharedMemorySize, SM64);
    cudaFuncSetAttribute((const void*)gemm2<128, 64, 32, 0>,
                         cudaFuncAttributeMaxDynamicSharedMemorySize, SM128);
    cudaFuncSetAttribute((const void*)gemm2<128, 64, 32, 1>,
                         cudaFuncAttributeMaxDynamicSharedMemorySize, SM128);
    cudaFuncSetAttribute((const void*)flash_attn,
                         cudaFuncAttributeMaxDynamicSharedMemorySize, SMFA);

    const float inv_div = 1.0f / 32.0f;
    const float inv_ws  = 1.0f / 1024.0f;
    dim3 tb(32, 8);

    // ---- weight prep ----
    prep_qkvw<<<(192 * DD + 255) / 256, 256>>>(Wq, Wk, Wv, bq, bk, bv);
    prep_wo<<<(DD * DKK + 255) / 256, 256>>>(Wo);
    transpose_split_f16<<<dim3(DFFN / 32, DD / 32), tb>>>(W1, w1fh, w1fl, DD, DFFN);
    transpose_split_f16<<<dim3(DD / 32, DFFN / 32), tb>>>(W2, w2fh, w2fl, DFFN, DD);
    colsum_kernel<<<DFFN / 256, 256>>>(W1, rsw1, DD, DFFN);

    embed_kernel<<<NTOT / 512, 256>>>(ids, emb);

    for (int it = 0; it < NREP; it++) {
        // QKV (input-norm folded): qkv = norm_B(y2) @ Wqkv^T + bqkv
        gemm2<64, 32, 32, 2><<<dim3(3, 128, 1), 256, SM64>>>(
            xfh, DD, wqkvfh, wqkvfl, DD, bqkv, statsB, rsqkv,
            0, 0, 0, qkvfh, qkvfl, 192, DD, inv_ws, 0, 0);

        // flash attention
        flash_attn<<<dim3(SS / 64, BB), 256, SMFA>>>(qkvfh, qkvfl, headf, inv_div);

        // y1 = head @ Wo_eff + bo + norm_B(y2-pair), pair out + LN partials
        gemm2<128, 64, 32, 0><<<dim3(4, 128, 1), 256, SM128>>>(
            headf, DKK, wofh, wofl, DKK, bo, 0, 0,
            xfh, xfl, statsB, x1fh, x1fl, DD, DKK, inv_ws, psum, psq);

        finalize_kernel<<<1, 256>>>(512, statsA);

        // h = relu(norm_A(y1) @ W1 + b1) (input-norm folded)
        gemm2<128, 64, 32, 1><<<dim3(16, 128, 1), 256, SM128>>>(
            x1fh, DD, w1fh, w1fl, DD, b1, statsA, rsw1,
            0, 0, 0, hf, 0, DFFN, DD, inv_ws, 0, 0);

        // y2 = h @ W2 + b2 + norm_A(y1-pair), pair out + LN partials
        gemm2<128, 64, 32, 0><<<dim3(4, 128, 1), 256, SM128>>>(
            hf, DFFN, w2fh, w2fl, DFFN, b2, 0, 0,
            x1fh, x1fl, statsA, xfh, xfl, DD, DFFN, inv_ws, psum, psq);

        finalize_kernel<<<1, 256>>>(512, statsB);
    }

    normalize_out<<<NTOT / 512, 256>>>(xfh, xfl, statsB, (float*)d_out);
}